// round 1
// baseline (speedup 1.0000x reference)
#include <cuda_runtime.h>
#include <cstddef>

// ---------------------------------------------------------------------------
// Problem constants (fixed shapes)
// ---------------------------------------------------------------------------
#define N0 200000
#define N1 100000
#define N2 50000
#define E0 1600000
#define E1 800000
#define F_IN 128
#define F_H  256
#define F_OUT 64

// ---------------------------------------------------------------------------
// Scratch (device globals; no allocation allowed)
// ---------------------------------------------------------------------------
__device__ float g_sum0[(size_t)N1 * F_IN];   // 51.2 MB  segment sums layer 1
__device__ float g_deg0[N1];
__device__ float g_h1[(size_t)N1 * F_H];      // 102.4 MB hidden activations
__device__ float g_sum1[(size_t)N2 * F_H];    // 51.2 MB  segment sums layer 2
__device__ float g_deg1[N2];

// ---------------------------------------------------------------------------
// Zero-fill (graph-capturable; avoids cudaMemsetAsync just in case)
// ---------------------------------------------------------------------------
__global__ void zero_kernel(float4* __restrict__ p, size_t n4) {
    size_t i = (size_t)blockIdx.x * blockDim.x + threadIdx.x;
    size_t stride = (size_t)gridDim.x * blockDim.x;
    float4 z = make_float4(0.f, 0.f, 0.f, 0.f);
    for (; i < n4; i += stride) p[i] = z;
}

// ---------------------------------------------------------------------------
// Segmented gather-sum. dst is sorted; each block handles CHUNK edges,
// accumulates in registers while dst stays constant, flushes with atomics
// only at segment boundaries. blockDim = F/4 (float4 per thread).
// ---------------------------------------------------------------------------
template <int F, int CHUNK>
__global__ void seg_gather_sum(const float4* __restrict__ feat,
                               const int* __restrict__ src,
                               const int* __restrict__ dst,
                               float* __restrict__ sum,
                               float* __restrict__ deg,
                               int nE) {
    constexpr int V = F / 4;
    const int tid = threadIdx.x;
    long e0 = (long)blockIdx.x * CHUNK;
    if (e0 >= nE) return;
    long e1 = e0 + CHUNK;
    if (e1 > nE) e1 = nE;

    int cur = dst[e0];
    float4 acc = make_float4(0.f, 0.f, 0.f, 0.f);
    float cnt = 0.f;

    for (long e = e0; e < e1; ++e) {
        int d = dst[e];
        if (d != cur) {
            float* s = sum + (size_t)cur * F + tid * 4;
            atomicAdd(s + 0, acc.x);
            atomicAdd(s + 1, acc.y);
            atomicAdd(s + 2, acc.z);
            atomicAdd(s + 3, acc.w);
            if (tid == 0) atomicAdd(&deg[cur], cnt);
            acc = make_float4(0.f, 0.f, 0.f, 0.f);
            cnt = 0.f;
            cur = d;
        }
        float4 v = feat[(size_t)src[e] * V + tid];
        acc.x += v.x; acc.y += v.y; acc.z += v.z; acc.w += v.w;
        cnt += 1.f;
    }
    // final flush
    float* s = sum + (size_t)cur * F + tid * 4;
    atomicAdd(s + 0, acc.x);
    atomicAdd(s + 1, acc.y);
    atomicAdd(s + 2, acc.z);
    atomicAdd(s + 3, acc.w);
    if (tid == 0) atomicAdd(&deg[cur], cnt);
}

// ---------------------------------------------------------------------------
// In-place mean: sum[row][*] /= max(deg[row], 1)
// ---------------------------------------------------------------------------
template <int F>
__global__ void mean_kernel(float4* __restrict__ sum,
                            const float* __restrict__ deg, int nRows) {
    constexpr int V = F / 4;
    size_t n4 = (size_t)nRows * V;
    size_t i = (size_t)blockIdx.x * blockDim.x + threadIdx.x;
    size_t stride = (size_t)gridDim.x * blockDim.x;
    for (; i < n4; i += stride) {
        int row = (int)(i / V);
        float inv = 1.f / fmaxf(deg[row], 1.f);
        float4 v = sum[i];
        v.x *= inv; v.y *= inv; v.z *= inv; v.w *= inv;
        sum[i] = v;
    }
}

// ---------------------------------------------------------------------------
// Fused concat-GEMM:  C[M,NN] = act( [A1|A2] @ [B1;B2] + bias )
//   A1: M x K1 row-major, A2: M x K2 row-major
//   B1: K1 x NN row-major, B2: K2 x NN row-major
// Tiled SIMT fp32 SGEMM, TM x TN micro-tile per thread.
// ---------------------------------------------------------------------------
template <int BM, int BN, int BK, int TM, int TN, int K1, int K2, int NN, bool RELU>
__global__ void __launch_bounds__((BM / TM) * (BN / TN))
gemm_fused(const float* __restrict__ A1, const float* __restrict__ A2,
           const float* __restrict__ B1, const float* __restrict__ B2,
           const float* __restrict__ bias, float* __restrict__ C, int M) {
    constexpr int THREADS = (BM / TM) * (BN / TN);
    __shared__ float As[BK][BM];
    __shared__ float Bs[BK][BN];

    const int tid = threadIdx.x;
    const int bm = blockIdx.x * BM;
    const int bn = blockIdx.y * BN;
    const int trow = tid / (BN / TN);
    const int tcol = tid % (BN / TN);

    float acc[TM][TN];
#pragma unroll
    for (int i = 0; i < TM; ++i)
#pragma unroll
        for (int j = 0; j < TN; ++j) acc[i][j] = 0.f;

    // A loader: float4 along K. BM * (BK/4) float4 total.
    constexpr int K4 = BK / 4;
    constexpr int A_LOADS = (BM * K4 + THREADS - 1) / THREADS;
    // B loader: float4 along N. BK * (BN/4) float4 total.
    constexpr int N4 = BN / 4;
    constexpr int B_F4 = BK * N4;

    constexpr int KT = (K1 + K2) / BK;
#pragma unroll 1
    for (int kt = 0; kt < KT; ++kt) {
        const int kg = kt * BK;
        const float* A; const float* B; int K; int kl;
        if (kg < K1) { A = A1; B = B1; K = K1; kl = kg; }
        else         { A = A2; B = B2; K = K2; kl = kg - K1; }

        // load A tile (transposed into As[k][m])
#pragma unroll
        for (int l = 0; l < A_LOADS; ++l) {
            int idx = tid + l * THREADS;
            if (idx < BM * K4) {
                int ar = idx / K4;
                int ac = idx % K4;
                int row = bm + ar;
                float4 v = make_float4(0.f, 0.f, 0.f, 0.f);
                if (row < M)
                    v = *(const float4*)(A + (size_t)row * K + kl + ac * 4);
                As[ac * 4 + 0][ar] = v.x;
                As[ac * 4 + 1][ar] = v.y;
                As[ac * 4 + 2][ar] = v.z;
                As[ac * 4 + 3][ar] = v.w;
            }
        }
        // load B tile
        if (B_F4 == THREADS || tid < B_F4) {
            int br = tid / N4;
            int bc = tid % N4;
            float4 w = *(const float4*)(B + (size_t)(kl + br) * NN + bn + bc * 4);
            *(float4*)&Bs[br][bc * 4] = w;
        }
        __syncthreads();

#pragma unroll
        for (int k = 0; k < BK; ++k) {
            float ra[TM], rb[TN];
#pragma unroll
            for (int i = 0; i < TM; ++i) ra[i] = As[k][trow * TM + i];
#pragma unroll
            for (int j = 0; j < TN; ++j) rb[j] = Bs[k][tcol * TN + j];
#pragma unroll
            for (int i = 0; i < TM; ++i)
#pragma unroll
                for (int j = 0; j < TN; ++j)
                    acc[i][j] = fmaf(ra[i], rb[j], acc[i][j]);
        }
        __syncthreads();
    }

    // epilogue: bias (+ReLU), float4 stores
#pragma unroll
    for (int i = 0; i < TM; ++i) {
        int row = bm + trow * TM + i;
        if (row >= M) continue;
#pragma unroll
        for (int j = 0; j < TN; j += 4) {
            int col = bn + tcol * TN + j;
            float4 v;
            v.x = acc[i][j + 0] + bias[col + 0];
            v.y = acc[i][j + 1] + bias[col + 1];
            v.z = acc[i][j + 2] + bias[col + 2];
            v.w = acc[i][j + 3] + bias[col + 3];
            if (RELU) {
                v.x = fmaxf(v.x, 0.f); v.y = fmaxf(v.y, 0.f);
                v.z = fmaxf(v.z, 0.f); v.w = fmaxf(v.w, 0.f);
            }
            *(float4*)(C + (size_t)row * NN + col) = v;
        }
    }
}

// ---------------------------------------------------------------------------
// Launch
// ---------------------------------------------------------------------------
extern "C" void kernel_launch(void* const* d_in, const int* in_sizes, int n_in,
                              void* d_out, int out_size) {
    const float* x    = (const float*)d_in[0];
    const int*   src0 = (const int*)d_in[1];
    const int*   dst0 = (const int*)d_in[2];
    const int*   src1 = (const int*)d_in[3];
    const int*   dst1 = (const int*)d_in[4];
    // d_in[5], d_in[6]: num_dst scalars (compile-time constants here)
    const float* Ws1  = (const float*)d_in[7];
    const float* Wn1  = (const float*)d_in[8];
    const float* b1   = (const float*)d_in[9];
    const float* Ws2  = (const float*)d_in[10];
    const float* Wn2  = (const float*)d_in[11];
    const float* b2   = (const float*)d_in[12];
    float*       out  = (float*)d_out;

    float *sum0, *deg0, *h1, *sum1, *deg1;
    cudaGetSymbolAddress((void**)&sum0, g_sum0);
    cudaGetSymbolAddress((void**)&deg0, g_deg0);
    cudaGetSymbolAddress((void**)&h1,   g_h1);
    cudaGetSymbolAddress((void**)&sum1, g_sum1);
    cudaGetSymbolAddress((void**)&deg1, g_deg1);

    // --- zero scratch ---
    {
        size_t n4 = (size_t)N1 * F_IN / 4;
        zero_kernel<<<2048, 256>>>((float4*)sum0, n4);
        zero_kernel<<<128, 256>>>((float4*)deg0, N1 / 4);
        zero_kernel<<<2048, 256>>>((float4*)sum1, (size_t)N2 * F_H / 4);
        zero_kernel<<<128, 256>>>((float4*)deg1, N2 / 4);
    }

    // --- layer 1: gather + segment sum (dst0 sorted) ---
    seg_gather_sum<F_IN, 64><<<E0 / 64, F_IN / 4>>>(
        (const float4*)x, src0, dst0, sum0, deg0, E0);
    mean_kernel<F_IN><<<2048, 256>>>((float4*)sum0, deg0, N1);

    // --- layer 1 fused GEMM: h1 = relu([x | mean0] @ [Ws1; Wn1] + b1) ---
    {
        dim3 grid((N1 + 127) / 128, F_H / 128);
        gemm_fused<128, 128, 8, 8, 8, F_IN, F_IN, F_H, true>
            <<<grid, 256>>>(x, sum0, Ws1, Wn1, b1, h1, N1);
    }

    // --- layer 2: gather + segment sum on h1 (dst1 sorted) ---
    seg_gather_sum<F_H, 64><<<(E1 + 63) / 64, F_H / 4>>>(
        (const float4*)h1, src1, dst1, sum1, deg1, E1);
    mean_kernel<F_H><<<2048, 256>>>((float4*)sum1, deg1, N2);

    // --- layer 2 fused GEMM: out = [h1 | mean1] @ [Ws2; Wn2] + b2 ---
    {
        dim3 grid((N2 + 127) / 128, F_OUT / 64);
        gemm_fused<128, 64, 8, 8, 4, F_H, F_H, F_OUT, false>
            <<<grid, 256>>>(h1, sum1, Ws2, Wn2, b2, out, N2);
    }
}

// round 3
// speedup vs baseline: 1.7276x; 1.7276x over previous
#include <cuda_runtime.h>
#include <cstdint>
#include <cstddef>

// ---------------------------------------------------------------------------
// Problem constants (fixed shapes)
// ---------------------------------------------------------------------------
#define N0 200000
#define N1 100000
#define N2 50000
#define E0 1600000
#define E1 800000
#define F_IN 128
#define F_H  256
#define F_OUT 64

// ---------------------------------------------------------------------------
// Scratch (device globals; no allocation allowed)
// ---------------------------------------------------------------------------
__device__ float g_sum0[(size_t)N1 * F_IN];       // layer-1 segment sums
__device__ float g_deg0[N1];
__device__ float g_h1[(size_t)N1 * F_H];          // hidden activations
__device__ float g_sum1[(size_t)N2 * F_H];        // layer-2 segment sums
__device__ float g_deg1[N2];
__device__ float g_Bt1[(size_t)F_H * (2 * F_IN)]; // [256 N x 256 K] transposed W1
__device__ float g_Bt2[(size_t)F_OUT * (2 * F_H)];// [64 N x 512 K] transposed W2

// ---------------------------------------------------------------------------
// Helpers
// ---------------------------------------------------------------------------
__device__ __forceinline__ uint32_t tf32_rn(float x) {
    uint32_t u;
    asm("cvt.rn.tf32.f32 %0, %1;" : "=r"(u) : "f"(x));
    return u;
}
__device__ __forceinline__ void mma_tf32(float* d, const uint32_t* a,
                                         const uint32_t* b, const float* c) {
    asm("mma.sync.aligned.m16n8k8.row.col.f32.tf32.tf32.f32 "
        "{%0,%1,%2,%3}, {%4,%5,%6,%7}, {%8,%9}, {%10,%11,%12,%13};"
        : "=f"(d[0]), "=f"(d[1]), "=f"(d[2]), "=f"(d[3])
        : "r"(a[0]), "r"(a[1]), "r"(a[2]), "r"(a[3]),
          "r"(b[0]), "r"(b[1]),
          "f"(c[0]), "f"(c[1]), "f"(c[2]), "f"(c[3]));
}

// ---------------------------------------------------------------------------
// Zero-fill
// ---------------------------------------------------------------------------
__global__ void zero_kernel(float4* __restrict__ p, size_t n4) {
    size_t i = (size_t)blockIdx.x * blockDim.x + threadIdx.x;
    size_t stride = (size_t)gridDim.x * blockDim.x;
    float4 z = make_float4(0.f, 0.f, 0.f, 0.f);
    for (; i < n4; i += stride) p[i] = z;
}

// ---------------------------------------------------------------------------
// Weight transpose + tf32 pre-round: Bt[n][k] = (k<K1 ? Ws[k][n] : Wn[k-K1][n])
// ---------------------------------------------------------------------------
template <int K1, int K2, int NN>
__global__ void transpose_w(const float* __restrict__ Ws, const float* __restrict__ Wn,
                            float* __restrict__ Bt) {
    int n = blockIdx.x;
    constexpr int KT = K1 + K2;
    for (int k = threadIdx.x; k < KT; k += blockDim.x) {
        float v = (k < K1) ? Ws[(size_t)k * NN + n] : Wn[(size_t)(k - K1) * NN + n];
        ((uint32_t*)Bt)[(size_t)n * KT + k] = tf32_rn(v);
    }
}

// ---------------------------------------------------------------------------
// Segmented gather-sum (dst sorted): register accumulation, boundary atomics
// ---------------------------------------------------------------------------
template <int F, int CHUNK>
__global__ void seg_gather_sum(const float4* __restrict__ feat,
                               const int* __restrict__ src,
                               const int* __restrict__ dst,
                               float* __restrict__ sum,
                               float* __restrict__ deg,
                               int nE) {
    constexpr int V = F / 4;
    const int tid = threadIdx.x;
    long e0 = (long)blockIdx.x * CHUNK;
    if (e0 >= nE) return;
    long e1 = e0 + CHUNK;
    if (e1 > nE) e1 = nE;

    int cur = dst[e0];
    float4 acc = make_float4(0.f, 0.f, 0.f, 0.f);
    float cnt = 0.f;

    for (long e = e0; e < e1; ++e) {
        int d = dst[e];
        if (d != cur) {
            float* s = sum + (size_t)cur * F + tid * 4;
            atomicAdd(s + 0, acc.x);
            atomicAdd(s + 1, acc.y);
            atomicAdd(s + 2, acc.z);
            atomicAdd(s + 3, acc.w);
            if (tid == 0) atomicAdd(&deg[cur], cnt);
            acc = make_float4(0.f, 0.f, 0.f, 0.f);
            cnt = 0.f;
            cur = d;
        }
        float4 v = feat[(size_t)src[e] * V + tid];
        acc.x += v.x; acc.y += v.y; acc.z += v.z; acc.w += v.w;
        cnt += 1.f;
    }
    float* s = sum + (size_t)cur * F + tid * 4;
    atomicAdd(s + 0, acc.x);
    atomicAdd(s + 1, acc.y);
    atomicAdd(s + 2, acc.z);
    atomicAdd(s + 3, acc.w);
    if (tid == 0) atomicAdd(&deg[cur], cnt);
}

// ---------------------------------------------------------------------------
// In-place mean
// ---------------------------------------------------------------------------
template <int F>
__global__ void mean_kernel(float4* __restrict__ sum,
                            const float* __restrict__ deg, int nRows) {
    constexpr int V = F / 4;
    size_t n4 = (size_t)nRows * V;
    size_t i = (size_t)blockIdx.x * blockDim.x + threadIdx.x;
    size_t stride = (size_t)gridDim.x * blockDim.x;
    for (; i < n4; i += stride) {
        int row = (int)(i / V);
        float inv = 1.f / fmaxf(deg[row], 1.f);
        float4 v = sum[i];
        v.x *= inv; v.y *= inv; v.z *= inv; v.w *= inv;
        sum[i] = v;
    }
}

// ---------------------------------------------------------------------------
// Warp-level tf32 mma.sync fused concat-GEMM
//   C[M, NTOT] = act([A1|A2] @ Bt^T + bias)
//   A1: M x K1 row-major fp32, A2: M x K2 row-major fp32 (RN-rounded here)
//   Bt: NTOT x (K1+K2) row-major, K-contiguous, pre-rounded tf32
// BM=128, BK=32, 256 threads = 8 warps as WARPS_M x WARPS_N.
// SMEM tiles padded to stride 36 floats (conflict-free fragment loads).
// ---------------------------------------------------------------------------
template <int BN, int WARPS_M, int WARPS_N, int K1, int K2, int NTOT, bool RELU>
__global__ void __launch_bounds__(256)
gemm_mma(const float* __restrict__ A1, const float* __restrict__ A2,
         const float* __restrict__ Bt, const float* __restrict__ bias,
         float* __restrict__ C, int M) {
    constexpr int BM = 128;
    constexpr int BK = 32;
    constexpr int ST = 36;                 // padded row stride (floats)
    constexpr int KTOT = K1 + K2;
    constexpr int KT = KTOT / BK;
    constexpr int WM = BM / WARPS_M;
    constexpr int WN = BN / WARPS_N;
    constexpr int WM16 = WM / 16;
    constexpr int WN8 = WN / 8;
    constexpr int APT = BM * BK / (4 * 256);   // float4 per thread (A tile)
    constexpr int BPT = BN * BK / (4 * 256);   // float4 per thread (B tile)
    constexpr int A_ST_SZ = BM * ST;           // floats per A stage
    constexpr int B_ST_SZ = BN * ST;

    extern __shared__ float sm[];
    float* Asm = sm;                       // 2 stages
    float* Bsm = sm + 2 * A_ST_SZ;         // 2 stages

    const int tid = threadIdx.x;
    const int lane = tid & 31;
    const int wid = tid >> 5;
    const int wm = wid / WARPS_N;
    const int wn = wid % WARPS_N;
    const int g = lane >> 2;               // group id (0..7)
    const int t = lane & 3;                // thread-in-group (0..3)
    const int bm = blockIdx.x * BM;
    const int bn = blockIdx.y * BN;

    float acc[WM16][WN8][4];
#pragma unroll
    for (int i = 0; i < WM16; ++i)
#pragma unroll
        for (int j = 0; j < WN8; ++j)
#pragma unroll
            for (int q = 0; q < 4; ++q) acc[i][j][q] = 0.f;

    float4 ra[APT], rb[BPT];

    auto load_chunk = [&](int c) {
        const int kb = c * BK;
        const float* A; int K, ko;
        if (kb < K1) { A = A1; K = K1; ko = kb; }
        else         { A = A2; K = K2; ko = kb - K1; }
#pragma unroll
        for (int i = 0; i < APT; ++i) {
            int idx = tid + i * 256;
            int r = idx >> 3, c4 = idx & 7;
            int gr = bm + r;
            ra[i] = (gr < M) ? *(const float4*)(A + (size_t)gr * K + ko + c4 * 4)
                             : make_float4(0.f, 0.f, 0.f, 0.f);
        }
#pragma unroll
        for (int i = 0; i < BPT; ++i) {
            int idx = tid + i * 256;
            int r = idx >> 3, c4 = idx & 7;
            rb[i] = *(const float4*)(Bt + (size_t)(bn + r) * KTOT + kb + c4 * 4);
        }
    };

    auto sts_chunk = [&](int s) {
        float* as = Asm + s * A_ST_SZ;
        float* bs = Bsm + s * B_ST_SZ;
#pragma unroll
        for (int i = 0; i < APT; ++i) {
            int idx = tid + i * 256;
            int r = idx >> 3, c4 = idx & 7;
            float4 v;
            v.x = __uint_as_float(tf32_rn(ra[i].x));
            v.y = __uint_as_float(tf32_rn(ra[i].y));
            v.z = __uint_as_float(tf32_rn(ra[i].z));
            v.w = __uint_as_float(tf32_rn(ra[i].w));
            *(float4*)(as + r * ST + c4 * 4) = v;
        }
#pragma unroll
        for (int i = 0; i < BPT; ++i) {
            int idx = tid + i * 256;
            int r = idx >> 3, c4 = idx & 7;
            *(float4*)(bs + r * ST + c4 * 4) = rb[i];
        }
    };

    auto compute = [&](int s) {
        const float* as = Asm + s * A_ST_SZ + (wm * WM) * ST;
        const float* bs = Bsm + s * B_ST_SZ + (wn * WN) * ST;
#pragma unroll
        for (int kk = 0; kk < BK; kk += 8) {
            uint32_t af[WM16][4];
#pragma unroll
            for (int mi = 0; mi < WM16; ++mi) {
                const float* p = as + (mi * 16 + g) * ST + kk + t;
                af[mi][0] = __float_as_uint(p[0]);
                af[mi][1] = __float_as_uint(p[8 * ST]);
                af[mi][2] = __float_as_uint(p[4]);
                af[mi][3] = __float_as_uint(p[8 * ST + 4]);
            }
            uint32_t bf[WN8][2];
#pragma unroll
            for (int ni = 0; ni < WN8; ++ni) {
                const float* p = bs + (ni * 8 + g) * ST + kk + t;
                bf[ni][0] = __float_as_uint(p[0]);
                bf[ni][1] = __float_as_uint(p[4]);
            }
#pragma unroll
            for (int mi = 0; mi < WM16; ++mi)
#pragma unroll
                for (int ni = 0; ni < WN8; ++ni)
                    mma_tf32(acc[mi][ni], af[mi], bf[ni], acc[mi][ni]);
        }
    };

    // Prologue
    load_chunk(0);
    sts_chunk(0);
    __syncthreads();

#pragma unroll 1
    for (int c = 0; c < KT; ++c) {
        if (c + 1 < KT) load_chunk(c + 1);
        compute(c & 1);
        if (c + 1 < KT) {
            sts_chunk((c + 1) & 1);
            __syncthreads();
        }
    }

    // Epilogue: bias (+ReLU), float2 stores
#pragma unroll
    for (int mi = 0; mi < WM16; ++mi) {
        int row0 = bm + wm * WM + mi * 16 + g;
#pragma unroll
        for (int ni = 0; ni < WN8; ++ni) {
            int col = bn + wn * WN + ni * 8 + 2 * t;
            float bx = bias[col], by = bias[col + 1];
            float2 v0, v1;
            v0.x = acc[mi][ni][0] + bx; v0.y = acc[mi][ni][1] + by;
            v1.x = acc[mi][ni][2] + bx; v1.y = acc[mi][ni][3] + by;
            if (RELU) {
                v0.x = fmaxf(v0.x, 0.f); v0.y = fmaxf(v0.y, 0.f);
                v1.x = fmaxf(v1.x, 0.f); v1.y = fmaxf(v1.y, 0.f);
            }
            if (row0 < M)     *(float2*)(C + (size_t)row0 * NTOT + col) = v0;
            if (row0 + 8 < M) *(float2*)(C + (size_t)(row0 + 8) * NTOT + col) = v1;
        }
    }
}

// ---------------------------------------------------------------------------
// Launch
// ---------------------------------------------------------------------------
extern "C" void kernel_launch(void* const* d_in, const int* in_sizes, int n_in,
                              void* d_out, int out_size) {
    const float* x    = (const float*)d_in[0];
    const int*   src0 = (const int*)d_in[1];
    const int*   dst0 = (const int*)d_in[2];
    const int*   src1 = (const int*)d_in[3];
    const int*   dst1 = (const int*)d_in[4];
    const float* Ws1  = (const float*)d_in[7];
    const float* Wn1  = (const float*)d_in[8];
    const float* b1   = (const float*)d_in[9];
    const float* Ws2  = (const float*)d_in[10];
    const float* Wn2  = (const float*)d_in[11];
    const float* b2   = (const float*)d_in[12];
    float*       out  = (float*)d_out;

    float *sum0, *deg0, *h1, *sum1, *deg1, *Bt1, *Bt2;
    cudaGetSymbolAddress((void**)&sum0, g_sum0);
    cudaGetSymbolAddress((void**)&deg0, g_deg0);
    cudaGetSymbolAddress((void**)&h1,   g_h1);
    cudaGetSymbolAddress((void**)&sum1, g_sum1);
    cudaGetSymbolAddress((void**)&deg1, g_deg1);
    cudaGetSymbolAddress((void**)&Bt1,  g_Bt1);
    cudaGetSymbolAddress((void**)&Bt2,  g_Bt2);

    // SMEM: 2 stages x (BM + BN) x 36 floats
    constexpr int SMEM1 = 2 * (128 * 36 + 128 * 36) * 4;  // 73728
    constexpr int SMEM2 = 2 * (128 * 36 + 64 * 36) * 4;   // 55296
    cudaFuncSetAttribute(gemm_mma<128, 2, 4, F_IN, F_IN, F_H, true>,
                         cudaFuncAttributeMaxDynamicSharedMemorySize, SMEM1);
    cudaFuncSetAttribute(gemm_mma<64, 4, 2, F_H, F_H, F_OUT, false>,
                         cudaFuncAttributeMaxDynamicSharedMemorySize, SMEM2);

    // --- zero scratch + prep transposed tf32 weights ---
    zero_kernel<<<2048, 256>>>((float4*)sum0, (size_t)N1 * F_IN / 4);
    zero_kernel<<<128, 256>>>((float4*)deg0, N1 / 4);
    zero_kernel<<<2048, 256>>>((float4*)sum1, (size_t)N2 * F_H / 4);
    zero_kernel<<<128, 256>>>((float4*)deg1, N2 / 4);
    transpose_w<F_IN, F_IN, F_H><<<F_H, 256>>>(Ws1, Wn1, Bt1);
    transpose_w<F_H, F_H, F_OUT><<<F_OUT, 256>>>(Ws2, Wn2, Bt2);

    // --- layer 1: gather + mean ---
    seg_gather_sum<F_IN, 64><<<E0 / 64, F_IN / 4>>>(
        (const float4*)x, src0, dst0, sum0, deg0, E0);
    mean_kernel<F_IN><<<2048, 256>>>((float4*)sum0, deg0, N1);

    // --- layer 1 GEMM: h1 = relu([x | mean0] @ W1 + b1) ---
    {
        dim3 grid((N1 + 127) / 128, F_H / 128);
        gemm_mma<128, 2, 4, F_IN, F_IN, F_H, true>
            <<<grid, 256, SMEM1>>>(x, sum0, Bt1, b1, h1, N1);
    }

    // --- layer 2: gather + mean on h1 ---
    seg_gather_sum<F_H, 64><<<(E1 + 63) / 64, F_H / 4>>>(
        (const float4*)h1, src1, dst1, sum1, deg1, E1);
    mean_kernel<F_H><<<2048, 256>>>((float4*)sum1, deg1, N2);

    // --- layer 2 GEMM: out = [h1 | mean1] @ W2 + b2 ---
    {
        dim3 grid((N2 + 127) / 128, F_OUT / 64);
        gemm_mma<64, 4, 2, F_H, F_H, F_OUT, false>
            <<<grid, 256, SMEM2>>>(h1, sum1, Bt2, b2, out, N2);
    }
}

// round 4
// speedup vs baseline: 1.7565x; 1.0167x over previous
#include <cuda_runtime.h>
#include <cstdint>
#include <cstddef>

// ---------------------------------------------------------------------------
// Problem constants (fixed shapes)
// ---------------------------------------------------------------------------
#define N0 200000
#define N1 100000
#define N2 50000
#define E0 1600000
#define E1 800000
#define F_IN 128
#define F_H  256
#define F_OUT 64

// ---------------------------------------------------------------------------
// Scratch (device globals; no allocation allowed)
// ---------------------------------------------------------------------------
__device__ float g_m0[(size_t)N1 * F_IN];          // layer-1 neighbor means
__device__ float g_h1[(size_t)N1 * F_H];           // hidden activations
__device__ float g_z2[(size_t)N1 * F_OUT];         // h1 @ Wn2
__device__ float g_m2[(size_t)N2 * F_OUT];         // gathered means of z2
__device__ int   g_rp0[N1 + 1];                    // CSR row ptr layer 1
__device__ int   g_rp1[N2 + 1];                    // CSR row ptr layer 2
__device__ float g_Bt1[(size_t)F_H * (2 * F_IN)];  // [256 N x 256 K] W1 concat, K-major
__device__ float g_Bt2s[(size_t)F_OUT * F_H];      // [64 N x 256 K] Ws2, K-major
__device__ float g_Bt2n[(size_t)F_OUT * F_H];      // [64 N x 256 K] Wn2, K-major
__device__ float g_zeros[F_OUT];                   // stays zero (zero-initialized)

// ---------------------------------------------------------------------------
// Helpers
// ---------------------------------------------------------------------------
__device__ __forceinline__ uint32_t tf32_rn(float x) {
    uint32_t u;
    asm("cvt.rn.tf32.f32 %0, %1;" : "=r"(u) : "f"(x));
    return u;
}
__device__ __forceinline__ void mma_tf32(float* d, const uint32_t* a,
                                         const uint32_t* b, const float* c) {
    asm("mma.sync.aligned.m16n8k8.row.col.f32.tf32.tf32.f32 "
        "{%0,%1,%2,%3}, {%4,%5,%6,%7}, {%8,%9}, {%10,%11,%12,%13};"
        : "=f"(d[0]), "=f"(d[1]), "=f"(d[2]), "=f"(d[3])
        : "r"(a[0]), "r"(a[1]), "r"(a[2]), "r"(a[3]),
          "r"(b[0]), "r"(b[1]),
          "f"(c[0]), "f"(c[1]), "f"(c[2]), "f"(c[3]));
}

// ---------------------------------------------------------------------------
// Weight transpose + tf32 pre-round (concat form; K2=0 => single matrix)
// ---------------------------------------------------------------------------
template <int K1, int K2, int NN>
__global__ void transpose_w(const float* __restrict__ Ws, const float* __restrict__ Wn,
                            float* __restrict__ Bt) {
    int n = blockIdx.x;
    constexpr int KT = K1 + K2;
    for (int k = threadIdx.x; k < KT; k += blockDim.x) {
        float v = (k < K1) ? Ws[(size_t)k * NN + n] : Wn[(size_t)(k - K1) * NN + n];
        ((uint32_t*)Bt)[(size_t)n * KT + k] = tf32_rn(v);
    }
}

// ---------------------------------------------------------------------------
// CSR row pointers from sorted dst: rp[n] = lower_bound(dst, n)
// ---------------------------------------------------------------------------
__global__ void row_ptr_kernel(const int* __restrict__ dst, int nE,
                               int* __restrict__ rp, int nNodes) {
    int n = blockIdx.x * blockDim.x + threadIdx.x;
    if (n > nNodes) return;
    int lo = 0, hi = nE;
    while (lo < hi) {
        int mid = (lo + hi) >> 1;
        if (dst[mid] < n) lo = mid + 1; else hi = mid;
    }
    rp[n] = lo;
}

// ---------------------------------------------------------------------------
// Direct gather-mean: V threads per node (V = F/4 float4 lanes), register
// accumulation, single write. No atomics, no zero pass.
// ---------------------------------------------------------------------------
template <int V>
__global__ void __launch_bounds__(256)
gather_mean(const float4* __restrict__ feat, const int* __restrict__ src,
            const int* __restrict__ rp, float4* __restrict__ out, int nNodes) {
    int t = blockIdx.x * blockDim.x + threadIdx.x;
    int gid = t / V;
    int lane = t % V;
    if (gid >= nNodes) return;
    int s = rp[gid], e = rp[gid + 1];
    float4 acc = make_float4(0.f, 0.f, 0.f, 0.f);
    int i = s;
    for (; i + 3 < e; i += 4) {
        int s0 = src[i], s1 = src[i + 1], s2 = src[i + 2], s3 = src[i + 3];
        float4 a = feat[(size_t)s0 * V + lane];
        float4 b = feat[(size_t)s1 * V + lane];
        float4 c = feat[(size_t)s2 * V + lane];
        float4 d = feat[(size_t)s3 * V + lane];
        acc.x += a.x + b.x + c.x + d.x;
        acc.y += a.y + b.y + c.y + d.y;
        acc.z += a.z + b.z + c.z + d.z;
        acc.w += a.w + b.w + c.w + d.w;
    }
    for (; i < e; ++i) {
        float4 a = feat[(size_t)src[i] * V + lane];
        acc.x += a.x; acc.y += a.y; acc.z += a.z; acc.w += a.w;
    }
    float inv = 1.f / fmaxf((float)(e - s), 1.f);
    acc.x *= inv; acc.y *= inv; acc.z *= inv; acc.w *= inv;
    out[(size_t)gid * V + lane] = acc;
}

// ---------------------------------------------------------------------------
// Warp-level tf32 mma.sync fused concat-GEMM
//   C[M, NTOT] = act([A1|A2] @ Bt^T + bias (+ addin))
// BM=128, BK=32, 256 threads = 8 warps as WARPS_M x WARPS_N.
// ---------------------------------------------------------------------------
template <int BN, int WARPS_M, int WARPS_N, int K1, int K2, int NTOT,
          bool RELU, bool ADDIN>
__global__ void __launch_bounds__(256)
gemm_mma(const float* __restrict__ A1, const float* __restrict__ A2,
         const float* __restrict__ Bt, const float* __restrict__ bias,
         const float* __restrict__ addin, float* __restrict__ C, int M) {
    constexpr int BM = 128;
    constexpr int BK = 32;
    constexpr int ST = 36;
    constexpr int KTOT = K1 + K2;
    constexpr int KT = KTOT / BK;
    constexpr int WM = BM / WARPS_M;
    constexpr int WN = BN / WARPS_N;
    constexpr int WM16 = WM / 16;
    constexpr int WN8 = WN / 8;
    constexpr int APT = BM * BK / (4 * 256);
    constexpr int BPT = BN * BK / (4 * 256);
    constexpr int A_ST_SZ = BM * ST;
    constexpr int B_ST_SZ = BN * ST;

    extern __shared__ float sm[];
    float* Asm = sm;
    float* Bsm = sm + 2 * A_ST_SZ;

    const int tid = threadIdx.x;
    const int lane = tid & 31;
    const int wid = tid >> 5;
    const int wm = wid / WARPS_N;
    const int wn = wid % WARPS_N;
    const int g = lane >> 2;
    const int t = lane & 3;
    const int bm = blockIdx.x * BM;
    const int bn = blockIdx.y * BN;

    float acc[WM16][WN8][4];
#pragma unroll
    for (int i = 0; i < WM16; ++i)
#pragma unroll
        for (int j = 0; j < WN8; ++j)
#pragma unroll
            for (int q = 0; q < 4; ++q) acc[i][j][q] = 0.f;

    float4 ra[APT], rb[BPT];

    auto load_chunk = [&](int c) {
        const int kb = c * BK;
        const float* A; int K, ko;
        if (kb < K1) { A = A1; K = K1; ko = kb; }
        else         { A = A2; K = K2; ko = kb - K1; }
#pragma unroll
        for (int i = 0; i < APT; ++i) {
            int idx = tid + i * 256;
            int r = idx >> 3, c4 = idx & 7;
            int gr = bm + r;
            ra[i] = (gr < M) ? *(const float4*)(A + (size_t)gr * K + ko + c4 * 4)
                             : make_float4(0.f, 0.f, 0.f, 0.f);
        }
#pragma unroll
        for (int i = 0; i < BPT; ++i) {
            int idx = tid + i * 256;
            int r = idx >> 3, c4 = idx & 7;
            rb[i] = *(const float4*)(Bt + (size_t)(bn + r) * KTOT + kb + c4 * 4);
        }
    };

    auto sts_chunk = [&](int s) {
        float* as = Asm + s * A_ST_SZ;
        float* bs = Bsm + s * B_ST_SZ;
#pragma unroll
        for (int i = 0; i < APT; ++i) {
            int idx = tid + i * 256;
            int r = idx >> 3, c4 = idx & 7;
            float4 v;
            v.x = __uint_as_float(tf32_rn(ra[i].x));
            v.y = __uint_as_float(tf32_rn(ra[i].y));
            v.z = __uint_as_float(tf32_rn(ra[i].z));
            v.w = __uint_as_float(tf32_rn(ra[i].w));
            *(float4*)(as + r * ST + c4 * 4) = v;
        }
#pragma unroll
        for (int i = 0; i < BPT; ++i) {
            int idx = tid + i * 256;
            int r = idx >> 3, c4 = idx & 7;
            *(float4*)(bs + r * ST + c4 * 4) = rb[i];
        }
    };

    auto compute = [&](int s) {
        const float* as = Asm + s * A_ST_SZ + (wm * WM) * ST;
        const float* bs = Bsm + s * B_ST_SZ + (wn * WN) * ST;
#pragma unroll
        for (int kk = 0; kk < BK; kk += 8) {
            uint32_t af[WM16][4];
#pragma unroll
            for (int mi = 0; mi < WM16; ++mi) {
                const float* p = as + (mi * 16 + g) * ST + kk + t;
                af[mi][0] = __float_as_uint(p[0]);
                af[mi][1] = __float_as_uint(p[8 * ST]);
                af[mi][2] = __float_as_uint(p[4]);
                af[mi][3] = __float_as_uint(p[8 * ST + 4]);
            }
            uint32_t bf[WN8][2];
#pragma unroll
            for (int ni = 0; ni < WN8; ++ni) {
                const float* p = bs + (ni * 8 + g) * ST + kk + t;
                bf[ni][0] = __float_as_uint(p[0]);
                bf[ni][1] = __float_as_uint(p[4]);
            }
#pragma unroll
            for (int mi = 0; mi < WM16; ++mi)
#pragma unroll
                for (int ni = 0; ni < WN8; ++ni)
                    mma_tf32(acc[mi][ni], af[mi], bf[ni], acc[mi][ni]);
        }
    };

    load_chunk(0);
    sts_chunk(0);
    __syncthreads();

#pragma unroll 1
    for (int c = 0; c < KT; ++c) {
        if (c + 1 < KT) load_chunk(c + 1);
        compute(c & 1);
        if (c + 1 < KT) {
            sts_chunk((c + 1) & 1);
            __syncthreads();
        }
    }

#pragma unroll
    for (int mi = 0; mi < WM16; ++mi) {
        int row0 = bm + wm * WM + mi * 16 + g;
#pragma unroll
        for (int ni = 0; ni < WN8; ++ni) {
            int col = bn + wn * WN + ni * 8 + 2 * t;
            float bx = bias[col], by = bias[col + 1];
            float2 v0, v1;
            v0.x = acc[mi][ni][0] + bx; v0.y = acc[mi][ni][1] + by;
            v1.x = acc[mi][ni][2] + bx; v1.y = acc[mi][ni][3] + by;
            if (ADDIN) {
                if (row0 < M) {
                    const float2 a0 = *(const float2*)(addin + (size_t)row0 * NTOT + col);
                    v0.x += a0.x; v0.y += a0.y;
                }
                if (row0 + 8 < M) {
                    const float2 a1 = *(const float2*)(addin + (size_t)(row0 + 8) * NTOT + col);
                    v1.x += a1.x; v1.y += a1.y;
                }
            }
            if (RELU) {
                v0.x = fmaxf(v0.x, 0.f); v0.y = fmaxf(v0.y, 0.f);
                v1.x = fmaxf(v1.x, 0.f); v1.y = fmaxf(v1.y, 0.f);
            }
            if (row0 < M)     *(float2*)(C + (size_t)row0 * NTOT + col) = v0;
            if (row0 + 8 < M) *(float2*)(C + (size_t)(row0 + 8) * NTOT + col) = v1;
        }
    }
}

// ---------------------------------------------------------------------------
// Launch
// ---------------------------------------------------------------------------
extern "C" void kernel_launch(void* const* d_in, const int* in_sizes, int n_in,
                              void* d_out, int out_size) {
    const float* x    = (const float*)d_in[0];
    const int*   src0 = (const int*)d_in[1];
    const int*   dst0 = (const int*)d_in[2];
    const int*   src1 = (const int*)d_in[3];
    const int*   dst1 = (const int*)d_in[4];
    const float* Ws1  = (const float*)d_in[7];
    const float* Wn1  = (const float*)d_in[8];
    const float* b1   = (const float*)d_in[9];
    const float* Ws2  = (const float*)d_in[10];
    const float* Wn2  = (const float*)d_in[11];
    const float* b2   = (const float*)d_in[12];
    float*       out  = (float*)d_out;

    float *m0, *h1, *z2, *m2, *Bt1, *Bt2s, *Bt2n, *zeros;
    int *rp0, *rp1;
    cudaGetSymbolAddress((void**)&m0,   g_m0);
    cudaGetSymbolAddress((void**)&h1,   g_h1);
    cudaGetSymbolAddress((void**)&z2,   g_z2);
    cudaGetSymbolAddress((void**)&m2,   g_m2);
    cudaGetSymbolAddress((void**)&rp0,  g_rp0);
    cudaGetSymbolAddress((void**)&rp1,  g_rp1);
    cudaGetSymbolAddress((void**)&Bt1,  g_Bt1);
    cudaGetSymbolAddress((void**)&Bt2s, g_Bt2s);
    cudaGetSymbolAddress((void**)&Bt2n, g_Bt2n);
    cudaGetSymbolAddress((void**)&zeros, g_zeros);

    constexpr int SMEM1 = 2 * (128 * 36 + 128 * 36) * 4;  // 73728
    constexpr int SMEM2 = 2 * (128 * 36 + 64 * 36) * 4;   // 55296
    cudaFuncSetAttribute(gemm_mma<128, 2, 4, F_IN, F_IN, F_H, true, false>,
                         cudaFuncAttributeMaxDynamicSharedMemorySize, SMEM1);
    cudaFuncSetAttribute(gemm_mma<64, 4, 2, F_H, 0, F_OUT, false, false>,
                         cudaFuncAttributeMaxDynamicSharedMemorySize, SMEM2);
    cudaFuncSetAttribute(gemm_mma<64, 4, 2, F_H, 0, F_OUT, false, true>,
                         cudaFuncAttributeMaxDynamicSharedMemorySize, SMEM2);

    // --- prep: transposed tf32 weights + CSR row pointers ---
    transpose_w<F_IN, F_IN, F_H><<<F_H, 256>>>(Ws1, Wn1, Bt1);
    transpose_w<F_H, 0, F_OUT><<<F_OUT, 256>>>(Ws2, Ws2, Bt2s);
    transpose_w<F_H, 0, F_OUT><<<F_OUT, 256>>>(Wn2, Wn2, Bt2n);
    row_ptr_kernel<<<(N1 + 256) / 256, 256>>>(dst0, E0, rp0, N1);
    row_ptr_kernel<<<(N2 + 256) / 256, 256>>>(dst1, E1, rp1, N2);

    // --- layer 1: direct gather-mean on x (128-wide) ---
    {
        constexpr int V = F_IN / 4;  // 32 threads per node
        long threads = (long)N1 * V;
        gather_mean<V><<<(int)((threads + 255) / 256), 256>>>(
            (const float4*)x, src0, rp0, (float4*)m0, N1);
    }

    // --- layer 1 GEMM: h1 = relu([x | m0] @ W1 + b1) ---
    {
        dim3 grid((N1 + 127) / 128, F_H / 128);
        gemm_mma<128, 2, 4, F_IN, F_IN, F_H, true, false>
            <<<grid, 256, SMEM1>>>(x, m0, Bt1, b1, nullptr, h1, N1);
    }

    // --- z2 = h1 @ Wn2 (all 100k rows, 64-wide) ---
    {
        dim3 grid((N1 + 127) / 128, 1);
        gemm_mma<64, 4, 2, F_H, 0, F_OUT, false, false>
            <<<grid, 256, SMEM2>>>(h1, h1, Bt2n, zeros, nullptr, z2, N1);
    }

    // --- layer 2: gather-mean on z2 (64-wide) ---
    {
        constexpr int V = F_OUT / 4;  // 16 threads per node
        long threads = (long)N2 * V;
        gather_mean<V><<<(int)((threads + 255) / 256), 256>>>(
            (const float4*)z2, src1, rp1, (float4*)m2, N2);
    }

    // --- out = h1[:50k] @ Ws2 + m2 + b2 ---
    {
        dim3 grid((N2 + 127) / 128, 1);
        gemm_mma<64, 4, 2, F_H, 0, F_OUT, false, true>
            <<<grid, 256, SMEM2>>>(h1, h1, Bt2s, b2, m2, out, N2);
    }
}

// round 5
// speedup vs baseline: 1.9267x; 1.0969x over previous
#include <cuda_runtime.h>
#include <cstdint>
#include <cstddef>

// ---------------------------------------------------------------------------
// Problem constants (fixed shapes)
// ---------------------------------------------------------------------------
#define N0 200000
#define N1 100000
#define N2 50000
#define E0 1600000
#define E1 800000
#define F_IN 128
#define F_H  256
#define F_OUT 64

// ---------------------------------------------------------------------------
// Scratch (device globals; no allocation allowed)
// ---------------------------------------------------------------------------
__device__ float g_m0[(size_t)N1 * F_IN];         // layer-1 neighbor means
__device__ float g_p1[(size_t)N1 * F_H];          // x @ Ws1 + b1
__device__ float g_h1[(size_t)N1 * F_H];          // hidden activations
__device__ float g_z2[(size_t)N1 * F_OUT];        // h1 @ Wn2
__device__ float g_m2[(size_t)N2 * F_OUT];        // gathered means of z2
__device__ int   g_rp0[N1 + 1];                   // CSR row ptr layer 1
__device__ int   g_rp1[N2 + 1];                   // CSR row ptr layer 2
__device__ float g_Bt1s[(size_t)F_H * F_IN];      // Ws1  [256N x 128K] K-major
__device__ float g_Bt1n[(size_t)F_H * F_IN];      // Wn1  [256N x 128K] K-major
__device__ float g_Bt2s[(size_t)F_OUT * F_H];     // Ws2  [64N x 256K]  K-major
__device__ float g_Bt2n[(size_t)F_OUT * F_H];     // Wn2  [64N x 256K]  K-major
__device__ float g_zeros[F_H];                    // stays zero

// ---------------------------------------------------------------------------
// Helpers
// ---------------------------------------------------------------------------
__device__ __forceinline__ uint32_t tf32_rn(float x) {
    uint32_t u;
    asm("cvt.rn.tf32.f32 %0, %1;" : "=r"(u) : "f"(x));
    return u;
}
__device__ __forceinline__ void mma_tf32(float* d, const uint32_t* a,
                                         const uint32_t* b, const float* c) {
    asm("mma.sync.aligned.m16n8k8.row.col.f32.tf32.tf32.f32 "
        "{%0,%1,%2,%3}, {%4,%5,%6,%7}, {%8,%9}, {%10,%11,%12,%13};"
        : "=f"(d[0]), "=f"(d[1]), "=f"(d[2]), "=f"(d[3])
        : "r"(a[0]), "r"(a[1]), "r"(a[2]), "r"(a[3]),
          "r"(b[0]), "r"(b[1]),
          "f"(c[0]), "f"(c[1]), "f"(c[2]), "f"(c[3]));
}

// ---------------------------------------------------------------------------
// Weight transpose + tf32 pre-round: Bt[n][k] = W[k][n]
// ---------------------------------------------------------------------------
template <int K, int NN>
__global__ void transpose_w(const float* __restrict__ W, float* __restrict__ Bt) {
    int n = blockIdx.x;
    for (int k = threadIdx.x; k < K; k += blockDim.x)
        ((uint32_t*)Bt)[(size_t)n * K + k] = tf32_rn(W[(size_t)k * NN + n]);
}

// ---------------------------------------------------------------------------
// CSR row pointers via boundary scatter (dst sorted, coalesced reads)
// ---------------------------------------------------------------------------
__global__ void row_ptr_scatter(const int* __restrict__ dst, int nE,
                                int* __restrict__ rp, int nNodes) {
    int i = blockIdx.x * blockDim.x + threadIdx.x;
    if (i >= nE) return;
    int d = dst[i];
    int prev = (i == 0) ? -1 : dst[i - 1];
    for (int n = prev + 1; n <= d; ++n) rp[n] = i;
    if (i == nE - 1)
        for (int n = d + 1; n <= nNodes; ++n) rp[n] = nE;
}

// ---------------------------------------------------------------------------
// Gather-mean device body: V float4-lanes per node
// ---------------------------------------------------------------------------
template <int V>
__device__ __forceinline__ void gather_device(
    int nodeBase, const float4* __restrict__ feat, const int* __restrict__ src,
    const int* __restrict__ rp, float4* __restrict__ out, int nNodes) {
    int local = threadIdx.x / V;
    int lane = threadIdx.x % V;
    int gid = nodeBase + local;
    if (gid >= nNodes) return;
    int s = rp[gid], e = rp[gid + 1];
    float4 acc = make_float4(0.f, 0.f, 0.f, 0.f);
    int i = s;
    for (; i + 3 < e; i += 4) {
        int s0 = src[i], s1 = src[i + 1], s2 = src[i + 2], s3 = src[i + 3];
        float4 a = feat[(size_t)s0 * V + lane];
        float4 b = feat[(size_t)s1 * V + lane];
        float4 c = feat[(size_t)s2 * V + lane];
        float4 d = feat[(size_t)s3 * V + lane];
        acc.x += a.x + b.x + c.x + d.x;
        acc.y += a.y + b.y + c.y + d.y;
        acc.z += a.z + b.z + c.z + d.z;
        acc.w += a.w + b.w + c.w + d.w;
    }
    for (; i < e; ++i) {
        float4 a = feat[(size_t)src[i] * V + lane];
        acc.x += a.x; acc.y += a.y; acc.z += a.z; acc.w += a.w;
    }
    float inv = 1.f / fmaxf((float)(e - s), 1.f);
    acc.x *= inv; acc.y *= inv; acc.z *= inv; acc.w *= inv;
    out[(size_t)gid * V + lane] = acc;
}

// ---------------------------------------------------------------------------
// tf32 mma.sync GEMM device body: C[bm:bm+128, bn:bn+BN] =
//   act(A @ Bt^T + bias (+ addin)).  256 threads, BK=32, double-buffered.
// ---------------------------------------------------------------------------
template <int BN, int WARPS_M, int WARPS_N, int K, int NTOT, bool RELU, bool ADDIN>
__device__ __forceinline__ void gemm_device(
    float* sm, int bm, int bn,
    const float* __restrict__ A, const float* __restrict__ Bt,
    const float* __restrict__ bias, const float* __restrict__ addin,
    float* __restrict__ C, int M) {
    constexpr int BM = 128;
    constexpr int BK = 32;
    constexpr int ST = 36;
    constexpr int KT = K / BK;
    constexpr int WM = BM / WARPS_M;
    constexpr int WN = BN / WARPS_N;
    constexpr int WM16 = WM / 16;
    constexpr int WN8 = WN / 8;
    constexpr int APT = BM * BK / (4 * 256);
    constexpr int BPT = BN * BK / (4 * 256);
    constexpr int A_ST_SZ = BM * ST;
    constexpr int B_ST_SZ = BN * ST;

    float* Asm = sm;
    float* Bsm = sm + 2 * A_ST_SZ;

    const int tid = threadIdx.x;
    const int lane = tid & 31;
    const int wid = tid >> 5;
    const int wm = wid / WARPS_N;
    const int wn = wid % WARPS_N;
    const int g = lane >> 2;
    const int t = lane & 3;

    float acc[WM16][WN8][4];
#pragma unroll
    for (int i = 0; i < WM16; ++i)
#pragma unroll
        for (int j = 0; j < WN8; ++j)
#pragma unroll
            for (int q = 0; q < 4; ++q) acc[i][j][q] = 0.f;

    float4 ra[APT], rb[BPT];

    auto load_chunk = [&](int c) {
        const int kb = c * BK;
#pragma unroll
        for (int i = 0; i < APT; ++i) {
            int idx = tid + i * 256;
            int r = idx >> 3, c4 = idx & 7;
            int gr = bm + r;
            ra[i] = (gr < M) ? *(const float4*)(A + (size_t)gr * K + kb + c4 * 4)
                             : make_float4(0.f, 0.f, 0.f, 0.f);
        }
#pragma unroll
        for (int i = 0; i < BPT; ++i) {
            int idx = tid + i * 256;
            int r = idx >> 3, c4 = idx & 7;
            rb[i] = *(const float4*)(Bt + (size_t)(bn + r) * K + kb + c4 * 4);
        }
    };

    auto sts_chunk = [&](int s) {
        float* as = Asm + s * A_ST_SZ;
        float* bs = Bsm + s * B_ST_SZ;
#pragma unroll
        for (int i = 0; i < APT; ++i) {
            int idx = tid + i * 256;
            int r = idx >> 3, c4 = idx & 7;
            float4 v;
            v.x = __uint_as_float(tf32_rn(ra[i].x));
            v.y = __uint_as_float(tf32_rn(ra[i].y));
            v.z = __uint_as_float(tf32_rn(ra[i].z));
            v.w = __uint_as_float(tf32_rn(ra[i].w));
            *(float4*)(as + r * ST + c4 * 4) = v;
        }
#pragma unroll
        for (int i = 0; i < BPT; ++i) {
            int idx = tid + i * 256;
            int r = idx >> 3, c4 = idx & 7;
            *(float4*)(bs + r * ST + c4 * 4) = rb[i];
        }
    };

    auto compute = [&](int s) {
        const float* as = Asm + s * A_ST_SZ + (wm * WM) * ST;
        const float* bs = Bsm + s * B_ST_SZ + (wn * WN) * ST;
#pragma unroll
        for (int kk = 0; kk < BK; kk += 8) {
            uint32_t af[WM16][4];
#pragma unroll
            for (int mi = 0; mi < WM16; ++mi) {
                const float* p = as + (mi * 16 + g) * ST + kk + t;
                af[mi][0] = __float_as_uint(p[0]);
                af[mi][1] = __float_as_uint(p[8 * ST]);
                af[mi][2] = __float_as_uint(p[4]);
                af[mi][3] = __float_as_uint(p[8 * ST + 4]);
            }
            uint32_t bf[WN8][2];
#pragma unroll
            for (int ni = 0; ni < WN8; ++ni) {
                const float* p = bs + (ni * 8 + g) * ST + kk + t;
                bf[ni][0] = __float_as_uint(p[0]);
                bf[ni][1] = __float_as_uint(p[4]);
            }
#pragma unroll
            for (int mi = 0; mi < WM16; ++mi)
#pragma unroll
                for (int ni = 0; ni < WN8; ++ni)
                    mma_tf32(acc[mi][ni], af[mi], bf[ni], acc[mi][ni]);
        }
    };

    load_chunk(0);
    sts_chunk(0);
    __syncthreads();

#pragma unroll 1
    for (int c = 0; c < KT; ++c) {
        if (c + 1 < KT) load_chunk(c + 1);
        compute(c & 1);
        if (c + 1 < KT) {
            sts_chunk((c + 1) & 1);
            __syncthreads();
        }
    }

#pragma unroll
    for (int mi = 0; mi < WM16; ++mi) {
        int row0 = bm + wm * WM + mi * 16 + g;
#pragma unroll
        for (int ni = 0; ni < WN8; ++ni) {
            int col = bn + wn * WN + ni * 8 + 2 * t;
            float bx = bias[col], by = bias[col + 1];
            float2 v0, v1;
            v0.x = acc[mi][ni][0] + bx; v0.y = acc[mi][ni][1] + by;
            v1.x = acc[mi][ni][2] + bx; v1.y = acc[mi][ni][3] + by;
            if (ADDIN) {
                if (row0 < M) {
                    const float2 a0 = *(const float2*)(addin + (size_t)row0 * NTOT + col);
                    v0.x += a0.x; v0.y += a0.y;
                }
                if (row0 + 8 < M) {
                    const float2 a1 = *(const float2*)(addin + (size_t)(row0 + 8) * NTOT + col);
                    v1.x += a1.x; v1.y += a1.y;
                }
            }
            if (RELU) {
                v0.x = fmaxf(v0.x, 0.f); v0.y = fmaxf(v0.y, 0.f);
                v1.x = fmaxf(v1.x, 0.f); v1.y = fmaxf(v1.y, 0.f);
            }
            if (row0 < M)     *(float2*)(C + (size_t)row0 * NTOT + col) = v0;
            if (row0 + 8 < M) *(float2*)(C + (size_t)(row0 + 8) * NTOT + col) = v1;
        }
    }
}

// ---------------------------------------------------------------------------
// Standalone GEMM kernel
// ---------------------------------------------------------------------------
template <int BN, int WARPS_M, int WARPS_N, int K, int NTOT, bool RELU, bool ADDIN>
__global__ void __launch_bounds__(256)
gemm_kernel(const float* __restrict__ A, const float* __restrict__ Bt,
            const float* __restrict__ bias, const float* __restrict__ addin,
            float* __restrict__ C, int M) {
    extern __shared__ float sm[];
    gemm_device<BN, WARPS_M, WARPS_N, K, NTOT, RELU, ADDIN>(
        sm, blockIdx.x * 128, blockIdx.y * BN, A, Bt, bias, addin, C, M);
}

// ---------------------------------------------------------------------------
// Heterogeneous kernel: first nGemm blocks run GEMM tiles, rest run gather.
// GEMM blocks come first so tensor work starts immediately; gather blocks
// backfill SMs as GEMM waves drain -> memory/tensor overlap.
// ---------------------------------------------------------------------------
template <int BN, int WARPS_M, int WARPS_N, int K, int NTOT, bool RELU,
          int GY, int V>
__global__ void __launch_bounds__(256)
fused_gemm_gather(const float* __restrict__ A, const float* __restrict__ Bt,
                  const float* __restrict__ bias, float* __restrict__ C, int M,
                  const float4* __restrict__ feat, const int* __restrict__ src,
                  const int* __restrict__ rp, float4* __restrict__ gout,
                  int nNodes, int nGemm) {
    extern __shared__ float sm[];
    int idx = blockIdx.x;
    if (idx < nGemm) {
        int bn_i = idx % GY;
        int bm_i = idx / GY;
        gemm_device<BN, WARPS_M, WARPS_N, K, NTOT, RELU, false>(
            sm, bm_i * 128, bn_i * BN, A, Bt, bias, nullptr, C, M);
    } else {
        constexpr int NPB = 256 / V;
        gather_device<V>((idx - nGemm) * NPB, feat, src, rp, gout, nNodes);
    }
}

// ---------------------------------------------------------------------------
// out = a + b (elementwise, float4)
// ---------------------------------------------------------------------------
__global__ void add_kernel(const float4* __restrict__ a,
                           const float4* __restrict__ b,
                           float4* __restrict__ o, int n4) {
    int i = blockIdx.x * blockDim.x + threadIdx.x;
    if (i >= n4) return;
    float4 va = a[i], vb = b[i];
    va.x += vb.x; va.y += vb.y; va.z += vb.z; va.w += vb.w;
    o[i] = va;
}

// ---------------------------------------------------------------------------
// Launch
// ---------------------------------------------------------------------------
extern "C" void kernel_launch(void* const* d_in, const int* in_sizes, int n_in,
                              void* d_out, int out_size) {
    const float* x    = (const float*)d_in[0];
    const int*   src0 = (const int*)d_in[1];
    const int*   dst0 = (const int*)d_in[2];
    const int*   src1 = (const int*)d_in[3];
    const int*   dst1 = (const int*)d_in[4];
    const float* Ws1  = (const float*)d_in[7];
    const float* Wn1  = (const float*)d_in[8];
    const float* b1   = (const float*)d_in[9];
    const float* Ws2  = (const float*)d_in[10];
    const float* Wn2  = (const float*)d_in[11];
    const float* b2   = (const float*)d_in[12];
    float*       out  = (float*)d_out;

    float *m0, *p1, *h1, *z2, *m2, *Bt1s, *Bt1n, *Bt2s, *Bt2n, *zeros;
    int *rp0, *rp1;
    cudaGetSymbolAddress((void**)&m0,   g_m0);
    cudaGetSymbolAddress((void**)&p1,   g_p1);
    cudaGetSymbolAddress((void**)&h1,   g_h1);
    cudaGetSymbolAddress((void**)&z2,   g_z2);
    cudaGetSymbolAddress((void**)&m2,   g_m2);
    cudaGetSymbolAddress((void**)&rp0,  g_rp0);
    cudaGetSymbolAddress((void**)&rp1,  g_rp1);
    cudaGetSymbolAddress((void**)&Bt1s, g_Bt1s);
    cudaGetSymbolAddress((void**)&Bt1n, g_Bt1n);
    cudaGetSymbolAddress((void**)&Bt2s, g_Bt2s);
    cudaGetSymbolAddress((void**)&Bt2n, g_Bt2n);
    cudaGetSymbolAddress((void**)&zeros, g_zeros);

    constexpr int SMEM_A = 2 * (128 * 36 + 128 * 36) * 4;  // 73728 (BN=128)
    constexpr int SMEM_C = 2 * (128 * 36 + 64 * 36) * 4;   // 55296 (BN=64)

    cudaFuncSetAttribute(
        (const void*)fused_gemm_gather<128, 2, 4, F_IN, F_H, false, 2, 32>,
        cudaFuncAttributeMaxDynamicSharedMemorySize, SMEM_A);
    cudaFuncSetAttribute(
        (const void*)gemm_kernel<128, 2, 4, F_IN, F_H, true, true>,
        cudaFuncAttributeMaxDynamicSharedMemorySize, SMEM_A);
    cudaFuncSetAttribute(
        (const void*)gemm_kernel<64, 4, 2, F_H, F_OUT, false, false>,
        cudaFuncAttributeMaxDynamicSharedMemorySize, SMEM_C);
    cudaFuncSetAttribute(
        (const void*)fused_gemm_gather<64, 4, 2, F_H, F_OUT, false, 1, 16>,
        cudaFuncAttributeMaxDynamicSharedMemorySize, SMEM_C);

    // --- prep: K-major tf32 weights + CSR row pointers ---
    transpose_w<F_IN, F_H><<<F_H, 128>>>(Ws1, Bt1s);
    transpose_w<F_IN, F_H><<<F_H, 128>>>(Wn1, Bt1n);
    transpose_w<F_H, F_OUT><<<F_OUT, 256>>>(Ws2, Bt2s);
    transpose_w<F_H, F_OUT><<<F_OUT, 256>>>(Wn2, Bt2n);
    row_ptr_scatter<<<(E0 + 255) / 256, 256>>>(dst0, E0, rp0, N1);
    row_ptr_scatter<<<(E1 + 255) / 256, 256>>>(dst1, E1, rp1, N2);

    // --- het A: gather1 (x -> m0)  ||  p1 = x @ Ws1 + b1 ---
    {
        constexpr int GY = F_H / 128;                  // 2
        int nGemm = ((N1 + 127) / 128) * GY;           // 1564
        int nGather = (N1 + 7) / 8;                    // 12500 (8 nodes/block)
        fused_gemm_gather<128, 2, 4, F_IN, F_H, false, GY, 32>
            <<<nGemm + nGather, 256, SMEM_A>>>(
                x, Bt1s, b1, p1, N1,
                (const float4*)x, src0, rp0, (float4*)m0, N1, nGemm);
    }

    // --- B: h1 = relu(m0 @ Wn1 + p1) ---
    {
        dim3 grid((N1 + 127) / 128, F_H / 128);
        gemm_kernel<128, 2, 4, F_IN, F_H, true, true>
            <<<grid, 256, SMEM_A>>>(m0, Bt1n, zeros, p1, h1, N1);
    }

    // --- C: z2 = h1 @ Wn2 ---
    {
        dim3 grid((N1 + 127) / 128, 1);
        gemm_kernel<64, 4, 2, F_H, F_OUT, false, false>
            <<<grid, 256, SMEM_C>>>(h1, Bt2n, zeros, nullptr, z2, N1);
    }

    // --- het D: gather2 (z2 -> m2)  ||  out = h1[:50k] @ Ws2 + b2 ---
    {
        int nGemm = (N2 + 127) / 128;                  // 391
        int nGather = (N2 + 15) / 16;                  // 3125 (16 nodes/block)
        fused_gemm_gather<64, 4, 2, F_H, F_OUT, false, 1, 16>
            <<<nGemm + nGather, 256, SMEM_C>>>(
                h1, Bt2s, b2, out, N2,
                (const float4*)z2, src1, rp1, (float4*)m2, N2, nGemm);
    }

    // --- E: out += m2 ---
    {
        int n4 = N2 * F_OUT / 4;
        add_kernel<<<(n4 + 255) / 256, 256>>>(
            (const float4*)out, (const float4*)m2, (float4*)out, n4);
    }
}

// round 6
// speedup vs baseline: 2.1329x; 1.1070x over previous
#include <cuda_runtime.h>
#include <cuda_fp16.h>
#include <cstdint>
#include <cstddef>

// ---------------------------------------------------------------------------
// Problem constants (fixed shapes)
// ---------------------------------------------------------------------------
#define N0 200000
#define N1 100000
#define N2 50000
#define E0 1600000
#define E1 800000
#define F_IN 128
#define F_H  256
#define F_OUT 64

// ---------------------------------------------------------------------------
// Scratch (device globals; no allocation allowed)
// ---------------------------------------------------------------------------
__device__ float  g_m0[(size_t)N1 * F_IN];        // layer-1 neighbor means (fp32)
__device__ __half g_p1[(size_t)N1 * F_H];         // x @ Ws1 + b1 (fp16)
__device__ __half g_h1[(size_t)N1 * F_H];         // hidden activations (fp16)
__device__ float  g_z2[(size_t)N1 * F_OUT];       // h1 @ Wn2 (fp32)
__device__ float  g_m2[(size_t)N2 * F_OUT];       // gathered means of z2
__device__ int    g_rp0[N1 + 1];                  // CSR row ptr layer 1
__device__ int    g_rp1[N2 + 1];                  // CSR row ptr layer 2
__device__ __half g_Bt1s[(size_t)F_H * F_IN];     // Ws1  [256N x 128K] K-major fp16
__device__ __half g_Bt1n[(size_t)F_H * F_IN];     // Wn1  [256N x 128K] K-major fp16
__device__ __half g_Bt2s[(size_t)F_OUT * F_H];    // Ws2  [64N x 256K]  K-major fp16
__device__ __half g_Bt2n[(size_t)F_OUT * F_H];    // Wn2  [64N x 256K]  K-major fp16
__device__ float  g_zeros[F_H];                   // stays zero

// ---------------------------------------------------------------------------
// Helpers
// ---------------------------------------------------------------------------
__device__ __forceinline__ void mma_f16(float* d, const uint32_t* a,
                                        const uint32_t* b, const float* c) {
    asm("mma.sync.aligned.m16n8k16.row.col.f32.f16.f16.f32 "
        "{%0,%1,%2,%3}, {%4,%5,%6,%7}, {%8,%9}, {%10,%11,%12,%13};"
        : "=f"(d[0]), "=f"(d[1]), "=f"(d[2]), "=f"(d[3])
        : "r"(a[0]), "r"(a[1]), "r"(a[2]), "r"(a[3]),
          "r"(b[0]), "r"(b[1]),
          "f"(c[0]), "f"(c[1]), "f"(c[2]), "f"(c[3]));
}
__device__ __forceinline__ uint32_t packh2(float x, float y) {
    __half2 h = __floats2half2_rn(x, y);
    return *(uint32_t*)&h;
}

// ---------------------------------------------------------------------------
// Weight transpose to K-major fp16: Bt[n][k] = W[k][n]
// ---------------------------------------------------------------------------
template <int K, int NN>
__global__ void transpose_w(const float* __restrict__ W, __half* __restrict__ Bt) {
    int n = blockIdx.x;
    for (int k = threadIdx.x; k < K; k += blockDim.x)
        Bt[(size_t)n * K + k] = __float2half(W[(size_t)k * NN + n]);
}

// ---------------------------------------------------------------------------
// CSR row pointers via boundary scatter (dst sorted, coalesced)
// ---------------------------------------------------------------------------
__global__ void row_ptr_scatter(const int* __restrict__ dst, int nE,
                                int* __restrict__ rp, int nNodes) {
    int i = blockIdx.x * blockDim.x + threadIdx.x;
    if (i >= nE) return;
    int d = dst[i];
    int prev = (i == 0) ? -1 : dst[i - 1];
    for (int n = prev + 1; n <= d; ++n) rp[n] = i;
    if (i == nE - 1)
        for (int n = d + 1; n <= nNodes; ++n) rp[n] = nE;
}

// ---------------------------------------------------------------------------
// Gather-mean device body: V float4-lanes per node
// ---------------------------------------------------------------------------
template <int V>
__device__ __forceinline__ void gather_device(
    int nodeBase, const float4* __restrict__ feat, const int* __restrict__ src,
    const int* __restrict__ rp, float4* __restrict__ out, int nNodes) {
    int local = threadIdx.x / V;
    int lane = threadIdx.x % V;
    int gid = nodeBase + local;
    if (gid >= nNodes) return;
    int s = rp[gid], e = rp[gid + 1];
    float4 acc = make_float4(0.f, 0.f, 0.f, 0.f);
    int i = s;
    for (; i + 3 < e; i += 4) {
        int s0 = src[i], s1 = src[i + 1], s2 = src[i + 2], s3 = src[i + 3];
        float4 a = feat[(size_t)s0 * V + lane];
        float4 b = feat[(size_t)s1 * V + lane];
        float4 c = feat[(size_t)s2 * V + lane];
        float4 d = feat[(size_t)s3 * V + lane];
        acc.x += a.x + b.x + c.x + d.x;
        acc.y += a.y + b.y + c.y + d.y;
        acc.z += a.z + b.z + c.z + d.z;
        acc.w += a.w + b.w + c.w + d.w;
    }
    for (; i < e; ++i) {
        float4 a = feat[(size_t)src[i] * V + lane];
        acc.x += a.x; acc.y += a.y; acc.z += a.z; acc.w += a.w;
    }
    float inv = 1.f / fmaxf((float)(e - s), 1.f);
    acc.x *= inv; acc.y *= inv; acc.z *= inv; acc.w *= inv;
    out[(size_t)gid * V + lane] = acc;
}

// ---------------------------------------------------------------------------
// fp16 m16n8k16 mma.sync GEMM device body
//   C[bm:bm+128, bn:bn+BN] = act(A @ Bt^T + bias (+ addin))
// A: fp32 (A_HALF=0, converted at staging) or fp16 (A_HALF=1), K-contig rows
// Bt: N x K fp16, K-major. OUT fp16 or fp32. 256 threads, BK=32, 2 stages.
// SMEM in uint32 (half2) units, row stride 20 => conflict-free frag loads.
// ---------------------------------------------------------------------------
template <int BN, int WARPS_M, int WARPS_N, int K, int NTOT, bool RELU,
          bool ADDIN, bool A_HALF, bool OUT_HALF>
__device__ __forceinline__ void gemm_device(
    uint32_t* smu, int bm, int bn,
    const void* __restrict__ Av, const __half* __restrict__ Bt,
    const float* __restrict__ bias, const __half* __restrict__ addin,
    void* __restrict__ Cv, int M) {
    constexpr int BM = 128;
    constexpr int BK = 32;                 // halfs per chunk
    constexpr int ST = 20;                 // uint32 row stride (16 data + 4 pad)
    constexpr int KT = K / BK;
    constexpr int WM = BM / WARPS_M;
    constexpr int WN = BN / WARPS_N;
    constexpr int WM16 = WM / 16;
    constexpr int WN8 = WN / 8;
    constexpr int A_ST_SZ = BM * ST;
    constexpr int B_ST_SZ = BN * ST;
    constexpr int APT_F = BM * BK / (4 * 256);   // float4 iters (fp32 A)
    constexpr int APT_H = BM * BK / (8 * 256);   // uint4 iters (fp16 A)
    constexpr int BPT_H = BN * BK / (8 * 256);   // uint4 iters (B)

    uint32_t* Asm = smu;
    uint32_t* Bsm = smu + 2 * A_ST_SZ;

    const int tid = threadIdx.x;
    const int lane = tid & 31;
    const int wid = tid >> 5;
    const int wm = wid / WARPS_N;
    const int wn = wid % WARPS_N;
    const int g = lane >> 2;
    const int t = lane & 3;

    float acc[WM16][WN8][4];
#pragma unroll
    for (int i = 0; i < WM16; ++i)
#pragma unroll
        for (int j = 0; j < WN8; ++j)
#pragma unroll
            for (int q = 0; q < 4; ++q) acc[i][j][q] = 0.f;

    float4 raf[A_HALF ? 1 : APT_F];
    uint4 rah[A_HALF ? APT_H : 1];
    uint4 rb[BPT_H];

    auto load_chunk = [&](int c) {
        const int kb = c * BK;
        if (!A_HALF) {
            const float* A = (const float*)Av;
#pragma unroll
            for (int i = 0; i < APT_F; ++i) {
                int idx = tid + i * 256;
                int r = idx >> 3, c4 = idx & 7;
                int gr = bm + r;
                raf[i] = (gr < M)
                    ? *(const float4*)(A + (size_t)gr * K + kb + c4 * 4)
                    : make_float4(0.f, 0.f, 0.f, 0.f);
            }
        } else {
            const __half* A = (const __half*)Av;
#pragma unroll
            for (int i = 0; i < APT_H; ++i) {
                int idx = tid + i * 256;
                int r = idx >> 2, c8 = idx & 3;
                int gr = bm + r;
                rah[i] = (gr < M)
                    ? *(const uint4*)(A + (size_t)gr * K + kb + c8 * 8)
                    : make_uint4(0u, 0u, 0u, 0u);
            }
        }
#pragma unroll
        for (int i = 0; i < BPT_H; ++i) {
            int idx = tid + i * 256;
            int r = idx >> 2, c8 = idx & 3;
            rb[i] = *(const uint4*)(Bt + (size_t)(bn + r) * K + kb + c8 * 8);
        }
    };

    auto sts_chunk = [&](int s) {
        uint32_t* as = Asm + s * A_ST_SZ;
        uint32_t* bs = Bsm + s * B_ST_SZ;
        if (!A_HALF) {
#pragma unroll
            for (int i = 0; i < APT_F; ++i) {
                int idx = tid + i * 256;
                int r = idx >> 3, c4 = idx & 7;
                uint2 h;
                h.x = packh2(raf[i].x, raf[i].y);
                h.y = packh2(raf[i].z, raf[i].w);
                *(uint2*)(as + r * ST + c4 * 2) = h;
            }
        } else {
#pragma unroll
            for (int i = 0; i < APT_H; ++i) {
                int idx = tid + i * 256;
                int r = idx >> 2, c8 = idx & 3;
                *(uint4*)(as + r * ST + c8 * 4) = rah[i];
            }
        }
#pragma unroll
        for (int i = 0; i < BPT_H; ++i) {
            int idx = tid + i * 256;
            int r = idx >> 2, c8 = idx & 3;
            *(uint4*)(bs + r * ST + c8 * 4) = rb[i];
        }
    };

    auto compute = [&](int s) {
        const uint32_t* as = Asm + s * A_ST_SZ + (wm * WM) * ST;
        const uint32_t* bs = Bsm + s * B_ST_SZ + (wn * WN) * ST;
#pragma unroll
        for (int kk2 = 0; kk2 < BK / 2; kk2 += 8) {   // two k16 steps per chunk
            uint32_t af[WM16][4];
#pragma unroll
            for (int mi = 0; mi < WM16; ++mi) {
                const uint32_t* p = as + (mi * 16 + g) * ST + kk2 + t;
                af[mi][0] = p[0];
                af[mi][1] = p[8 * ST];
                af[mi][2] = p[4];
                af[mi][3] = p[8 * ST + 4];
            }
            uint32_t bf[WN8][2];
#pragma unroll
            for (int ni = 0; ni < WN8; ++ni) {
                const uint32_t* p = bs + (ni * 8 + g) * ST + kk2 + t;
                bf[ni][0] = p[0];
                bf[ni][1] = p[4];
            }
#pragma unroll
            for (int mi = 0; mi < WM16; ++mi)
#pragma unroll
                for (int ni = 0; ni < WN8; ++ni)
                    mma_f16(acc[mi][ni], af[mi], bf[ni], acc[mi][ni]);
        }
    };

    load_chunk(0);
    sts_chunk(0);
    __syncthreads();

#pragma unroll 1
    for (int c = 0; c < KT; ++c) {
        if (c + 1 < KT) load_chunk(c + 1);
        compute(c & 1);
        if (c + 1 < KT) {
            sts_chunk((c + 1) & 1);
            __syncthreads();
        }
    }

    // Epilogue
#pragma unroll
    for (int mi = 0; mi < WM16; ++mi) {
        int row0 = bm + wm * WM + mi * 16 + g;
#pragma unroll
        for (int ni = 0; ni < WN8; ++ni) {
            int col = bn + wn * WN + ni * 8 + 2 * t;
            float bx = bias[col], by = bias[col + 1];
            float2 v0, v1;
            v0.x = acc[mi][ni][0] + bx; v0.y = acc[mi][ni][1] + by;
            v1.x = acc[mi][ni][2] + bx; v1.y = acc[mi][ni][3] + by;
            if (ADDIN) {
                if (row0 < M) {
                    float2 a0 = __half22float2(
                        *(const __half2*)(addin + (size_t)row0 * NTOT + col));
                    v0.x += a0.x; v0.y += a0.y;
                }
                if (row0 + 8 < M) {
                    float2 a1 = __half22float2(
                        *(const __half2*)(addin + (size_t)(row0 + 8) * NTOT + col));
                    v1.x += a1.x; v1.y += a1.y;
                }
            }
            if (RELU) {
                v0.x = fmaxf(v0.x, 0.f); v0.y = fmaxf(v0.y, 0.f);
                v1.x = fmaxf(v1.x, 0.f); v1.y = fmaxf(v1.y, 0.f);
            }
            if (OUT_HALF) {
                __half* C = (__half*)Cv;
                if (row0 < M)
                    *(__half2*)(C + (size_t)row0 * NTOT + col) =
                        __floats2half2_rn(v0.x, v0.y);
                if (row0 + 8 < M)
                    *(__half2*)(C + (size_t)(row0 + 8) * NTOT + col) =
                        __floats2half2_rn(v1.x, v1.y);
            } else {
                float* C = (float*)Cv;
                if (row0 < M)     *(float2*)(C + (size_t)row0 * NTOT + col) = v0;
                if (row0 + 8 < M) *(float2*)(C + (size_t)(row0 + 8) * NTOT + col) = v1;
            }
        }
    }
}

// ---------------------------------------------------------------------------
// Standalone GEMM kernel
// ---------------------------------------------------------------------------
template <int BN, int WARPS_M, int WARPS_N, int K, int NTOT, bool RELU,
          bool ADDIN, bool A_HALF, bool OUT_HALF>
__global__ void __launch_bounds__(256, 2)
gemm_kernel(const void* __restrict__ A, const __half* __restrict__ Bt,
            const float* __restrict__ bias, const __half* __restrict__ addin,
            void* __restrict__ C, int M) {
    extern __shared__ uint32_t smu[];
    gemm_device<BN, WARPS_M, WARPS_N, K, NTOT, RELU, ADDIN, A_HALF, OUT_HALF>(
        smu, blockIdx.x * 128, blockIdx.y * BN, A, Bt, bias, addin, C, M);
}

// ---------------------------------------------------------------------------
// Heterogeneous kernel: first nGemm blocks = GEMM tiles, rest = gather.
// ---------------------------------------------------------------------------
template <int BN, int WARPS_M, int WARPS_N, int K, int NTOT, bool RELU,
          bool A_HALF, bool OUT_HALF, int GY, int V>
__global__ void __launch_bounds__(256, 2)
fused_gemm_gather(const void* __restrict__ A, const __half* __restrict__ Bt,
                  const float* __restrict__ bias, void* __restrict__ C, int M,
                  const float4* __restrict__ feat, const int* __restrict__ src,
                  const int* __restrict__ rp, float4* __restrict__ gout,
                  int nNodes, int nGemm) {
    extern __shared__ uint32_t smu[];
    int idx = blockIdx.x;
    if (idx < nGemm) {
        int bn_i = idx % GY;
        int bm_i = idx / GY;
        gemm_device<BN, WARPS_M, WARPS_N, K, NTOT, RELU, false, A_HALF, OUT_HALF>(
            smu, bm_i * 128, bn_i * BN, A, Bt, bias, nullptr, C, M);
    } else {
        constexpr int NPB = 256 / V;
        gather_device<V>((idx - nGemm) * NPB, feat, src, rp, gout, nNodes);
    }
}

// ---------------------------------------------------------------------------
// out = a + b (elementwise, float4)
// ---------------------------------------------------------------------------
__global__ void add_kernel(const float4* __restrict__ a,
                           const float4* __restrict__ b,
                           float4* __restrict__ o, int n4) {
    int i = blockIdx.x * blockDim.x + threadIdx.x;
    if (i >= n4) return;
    float4 va = a[i], vb = b[i];
    va.x += vb.x; va.y += vb.y; va.z += vb.z; va.w += vb.w;
    o[i] = va;
}

// ---------------------------------------------------------------------------
// Launch
// ---------------------------------------------------------------------------
extern "C" void kernel_launch(void* const* d_in, const int* in_sizes, int n_in,
                              void* d_out, int out_size) {
    const float* x    = (const float*)d_in[0];
    const int*   src0 = (const int*)d_in[1];
    const int*   dst0 = (const int*)d_in[2];
    const int*   src1 = (const int*)d_in[3];
    const int*   dst1 = (const int*)d_in[4];
    const float* Ws1  = (const float*)d_in[7];
    const float* Wn1  = (const float*)d_in[8];
    const float* b1   = (const float*)d_in[9];
    const float* Ws2  = (const float*)d_in[10];
    const float* Wn2  = (const float*)d_in[11];
    const float* b2   = (const float*)d_in[12];
    float*       out  = (float*)d_out;

    float *m0, *z2, *m2, *zeros;
    __half *p1, *h1, *Bt1s, *Bt1n, *Bt2s, *Bt2n;
    int *rp0, *rp1;
    cudaGetSymbolAddress((void**)&m0,   g_m0);
    cudaGetSymbolAddress((void**)&p1,   g_p1);
    cudaGetSymbolAddress((void**)&h1,   g_h1);
    cudaGetSymbolAddress((void**)&z2,   g_z2);
    cudaGetSymbolAddress((void**)&m2,   g_m2);
    cudaGetSymbolAddress((void**)&rp0,  g_rp0);
    cudaGetSymbolAddress((void**)&rp1,  g_rp1);
    cudaGetSymbolAddress((void**)&Bt1s, g_Bt1s);
    cudaGetSymbolAddress((void**)&Bt1n, g_Bt1n);
    cudaGetSymbolAddress((void**)&Bt2s, g_Bt2s);
    cudaGetSymbolAddress((void**)&Bt2n, g_Bt2n);
    cudaGetSymbolAddress((void**)&zeros, g_zeros);

    // SMEM (uint32 units, stride 20): 2*(BM+BN)*20*4 bytes
    constexpr int SMEM_128 = 2 * (128 * 20 + 128 * 20) * 4;  // 40960
    constexpr int SMEM_64  = 2 * (128 * 20 + 64 * 20) * 4;   // 30720

    // --- prep: K-major fp16 weights + CSR row pointers ---
    transpose_w<F_IN, F_H><<<F_H, 128>>>(Ws1, Bt1s);
    transpose_w<F_IN, F_H><<<F_H, 128>>>(Wn1, Bt1n);
    transpose_w<F_H, F_OUT><<<F_OUT, 256>>>(Ws2, Bt2s);
    transpose_w<F_H, F_OUT><<<F_OUT, 256>>>(Wn2, Bt2n);
    row_ptr_scatter<<<(E0 + 255) / 256, 256>>>(dst0, E0, rp0, N1);
    row_ptr_scatter<<<(E1 + 255) / 256, 256>>>(dst1, E1, rp1, N2);

    // --- het A: gather1 (x -> m0)  ||  p1 = x @ Ws1 + b1 (fp16 out) ---
    {
        constexpr int GY = F_H / 128;                  // 2
        int nGemm = ((N1 + 127) / 128) * GY;           // 1564
        int nGather = (N1 + 7) / 8;                    // 12500
        fused_gemm_gather<128, 2, 4, F_IN, F_H, false, false, true, GY, 32>
            <<<nGemm + nGather, 256, SMEM_128>>>(
                x, Bt1s, b1, p1, N1,
                (const float4*)x, src0, rp0, (float4*)m0, N1, nGemm);
    }

    // --- B: h1 = relu(m0 @ Wn1 + p1)  (fp16 out) ---
    {
        dim3 grid((N1 + 127) / 128, F_H / 128);
        gemm_kernel<128, 2, 4, F_IN, F_H, true, true, false, true>
            <<<grid, 256, SMEM_128>>>(m0, Bt1n, zeros, p1, h1, N1);
    }

    // --- C: z2 = h1 @ Wn2  (fp32 out) ---
    {
        dim3 grid((N1 + 127) / 128, 1);
        gemm_kernel<64, 4, 2, F_H, F_OUT, false, false, true, false>
            <<<grid, 256, SMEM_64>>>(h1, Bt2n, zeros, nullptr, z2, N1);
    }

    // --- het D: gather2 (z2 -> m2)  ||  out = h1[:50k] @ Ws2 + b2 ---
    {
        int nGemm = (N2 + 127) / 128;                  // 391
        int nGather = (N2 + 15) / 16;                  // 3125
        fused_gemm_gather<64, 4, 2, F_H, F_OUT, false, true, false, 1, 16>
            <<<nGemm + nGather, 256, SMEM_64>>>(
                h1, Bt2s, b2, out, N2,
                (const float4*)z2, src1, rp1, (float4*)m2, N2, nGemm);
    }

    // --- E: out += m2 ---
    {
        int n4 = N2 * F_OUT / 4;
        add_kernel<<<(n4 + 255) / 256, 256>>>(
            (const float4*)out, (const float4*)m2, (float4*)out, n4);
    }
}

// round 7
// speedup vs baseline: 2.2733x; 1.0658x over previous
#include <cuda_runtime.h>
#include <cuda_fp16.h>
#include <cstdint>
#include <cstddef>

// ---------------------------------------------------------------------------
// Problem constants (fixed shapes)
// ---------------------------------------------------------------------------
#define N0 200000
#define N1 100000
#define N2 50000
#define E0 1600000
#define E1 800000
#define F_IN 128
#define F_H  256
#define F_OUT 64

// ---------------------------------------------------------------------------
// Scratch (device globals; no allocation allowed)
// ---------------------------------------------------------------------------
__device__ __half g_m0[(size_t)N1 * F_IN];        // layer-1 neighbor means (fp16)
__device__ __half g_p1[(size_t)N1 * F_H];         // x @ Ws1 + b1 (fp16)
__device__ __half g_h1[(size_t)N1 * F_H];         // hidden activations (fp16)
__device__ __half g_z2[(size_t)N1 * F_OUT];       // h1 @ Wn2 (fp16)
__device__ float  g_m2[(size_t)N2 * F_OUT];       // gathered means of z2 (fp32)
__device__ int    g_rp0[N1 + 1];                  // CSR row ptr layer 1
__device__ int    g_rp1[N2 + 1];                  // CSR row ptr layer 2
__device__ __half g_Bt1s[(size_t)F_H * F_IN];     // Ws1  [256N x 128K] K-major fp16
__device__ __half g_Bt1n[(size_t)F_H * F_IN];     // Wn1  [256N x 128K] K-major fp16
__device__ __half g_Bt2s[(size_t)F_OUT * F_H];    // Ws2  [64N x 256K]  K-major fp16
__device__ __half g_Bt2n[(size_t)F_OUT * F_H];    // Wn2  [64N x 256K]  K-major fp16
__device__ float  g_zeros[F_H];                   // stays zero

// ---------------------------------------------------------------------------
// Helpers
// ---------------------------------------------------------------------------
__device__ __forceinline__ void mma_f16(float* d, const uint32_t* a,
                                        const uint32_t* b, const float* c) {
    asm("mma.sync.aligned.m16n8k16.row.col.f32.f16.f16.f32 "
        "{%0,%1,%2,%3}, {%4,%5,%6,%7}, {%8,%9}, {%10,%11,%12,%13};"
        : "=f"(d[0]), "=f"(d[1]), "=f"(d[2]), "=f"(d[3])
        : "r"(a[0]), "r"(a[1]), "r"(a[2]), "r"(a[3]),
          "r"(b[0]), "r"(b[1]),
          "f"(c[0]), "f"(c[1]), "f"(c[2]), "f"(c[3]));
}
__device__ __forceinline__ void ldsm_x4(uint32_t& r0, uint32_t& r1,
                                        uint32_t& r2, uint32_t& r3,
                                        uint32_t saddr) {
    asm volatile("ldmatrix.sync.aligned.m8n8.x4.shared.b16 {%0,%1,%2,%3}, [%4];"
                 : "=r"(r0), "=r"(r1), "=r"(r2), "=r"(r3) : "r"(saddr));
}
__device__ __forceinline__ uint32_t packh2(float x, float y) {
    __half2 h = __floats2half2_rn(x, y);
    return *(uint32_t*)&h;
}

// ---------------------------------------------------------------------------
// Fused prep kernel: CSR scatter (both layers) + 4 weight transposes.
// Block ranges: [0,6250) rp0 | [6250,9375) rp1 | 256 t1s | 256 t1n | 64 t2s | 64 t2n
// ---------------------------------------------------------------------------
#define NB_RP0 ((E0 + 255) / 256)
#define NB_RP1 ((E1 + 255) / 256)
__global__ void __launch_bounds__(256)
prep_kernel(const int* __restrict__ dst0, const int* __restrict__ dst1,
            const float* __restrict__ Ws1, const float* __restrict__ Wn1,
            const float* __restrict__ Ws2, const float* __restrict__ Wn2,
            int* __restrict__ rp0, int* __restrict__ rp1,
            __half* __restrict__ Bt1s, __half* __restrict__ Bt1n,
            __half* __restrict__ Bt2s, __half* __restrict__ Bt2n) {
    int b = blockIdx.x, tid = threadIdx.x;
    if (b < NB_RP0) {
        int i = b * 256 + tid;
        if (i < E0) {
            int d = dst0[i];
            int prev = (i == 0) ? -1 : dst0[i - 1];
            for (int n = prev + 1; n <= d; ++n) rp0[n] = i;
            if (i == E0 - 1)
                for (int n = d + 1; n <= N1; ++n) rp0[n] = E0;
        }
    } else if (b < NB_RP0 + NB_RP1) {
        int i = (b - NB_RP0) * 256 + tid;
        if (i < E1) {
            int d = dst1[i];
            int prev = (i == 0) ? -1 : dst1[i - 1];
            for (int n = prev + 1; n <= d; ++n) rp1[n] = i;
            if (i == E1 - 1)
                for (int n = d + 1; n <= N2; ++n) rp1[n] = E1;
        }
    } else if (b < NB_RP0 + NB_RP1 + 256) {
        int n = b - (NB_RP0 + NB_RP1);
        if (tid < F_IN) Bt1s[(size_t)n * F_IN + tid] =
            __float2half(Ws1[(size_t)tid * F_H + n]);
    } else if (b < NB_RP0 + NB_RP1 + 512) {
        int n = b - (NB_RP0 + NB_RP1 + 256);
        if (tid < F_IN) Bt1n[(size_t)n * F_IN + tid] =
            __float2half(Wn1[(size_t)tid * F_H + n]);
    } else if (b < NB_RP0 + NB_RP1 + 576) {
        int n = b - (NB_RP0 + NB_RP1 + 512);
        Bt2s[(size_t)n * F_H + tid] = __float2half(Ws2[(size_t)tid * F_OUT + n]);
    } else {
        int n = b - (NB_RP0 + NB_RP1 + 576);
        Bt2n[(size_t)n * F_H + tid] = __float2half(Wn2[(size_t)tid * F_OUT + n]);
    }
}

// ---------------------------------------------------------------------------
// Gather-mean bodies
// ---------------------------------------------------------------------------
// fp32 float4 feat -> fp16 out (4 halfs = uint2 per lane). V lanes per node.
template <int V>
__device__ __forceinline__ void gather_f32_to_f16(
    int nodeBase, const float4* __restrict__ feat, const int* __restrict__ src,
    const int* __restrict__ rp, uint2* __restrict__ out, int nNodes) {
    int local = threadIdx.x / V;
    int lane = threadIdx.x % V;
    int gid = nodeBase + local;
    if (gid >= nNodes) return;
    int s = rp[gid], e = rp[gid + 1];
    float4 acc = make_float4(0.f, 0.f, 0.f, 0.f);
    int i = s;
    for (; i + 3 < e; i += 4) {
        int s0 = src[i], s1 = src[i + 1], s2 = src[i + 2], s3 = src[i + 3];
        float4 a = feat[(size_t)s0 * V + lane];
        float4 b = feat[(size_t)s1 * V + lane];
        float4 c = feat[(size_t)s2 * V + lane];
        float4 d = feat[(size_t)s3 * V + lane];
        acc.x += a.x + b.x + c.x + d.x;
        acc.y += a.y + b.y + c.y + d.y;
        acc.z += a.z + b.z + c.z + d.z;
        acc.w += a.w + b.w + c.w + d.w;
    }
    for (; i < e; ++i) {
        float4 a = feat[(size_t)src[i] * V + lane];
        acc.x += a.x; acc.y += a.y; acc.z += a.z; acc.w += a.w;
    }
    float inv = 1.f / fmaxf((float)(e - s), 1.f);
    uint2 h;
    h.x = packh2(acc.x * inv, acc.y * inv);
    h.y = packh2(acc.z * inv, acc.w * inv);
    out[(size_t)gid * V + lane] = h;
}

// fp16 feat (uint2 = 4 halfs per lane) -> fp32 float4 out. V lanes per node.
template <int V>
__device__ __forceinline__ void gather_f16_to_f32(
    int nodeBase, const uint2* __restrict__ feat, const int* __restrict__ src,
    const int* __restrict__ rp, float4* __restrict__ out, int nNodes) {
    int local = threadIdx.x / V;
    int lane = threadIdx.x % V;
    int gid = nodeBase + local;
    if (gid >= nNodes) return;
    int s = rp[gid], e = rp[gid + 1];
    float4 acc = make_float4(0.f, 0.f, 0.f, 0.f);
    for (int i = s; i < e; ++i) {
        uint2 u = feat[(size_t)src[i] * V + lane];
        float2 lo = __half22float2(*(__half2*)&u.x);
        float2 hi = __half22float2(*(__half2*)&u.y);
        acc.x += lo.x; acc.y += lo.y; acc.z += hi.x; acc.w += hi.y;
    }
    float inv = 1.f / fmaxf((float)(e - s), 1.f);
    acc.x *= inv; acc.y *= inv; acc.z *= inv; acc.w *= inv;
    out[(size_t)gid * V + lane] = acc;
}

// ---------------------------------------------------------------------------
// fp16 m16n8k16 mma.sync GEMM device body (ldmatrix fragment loads)
//   C[bm:bm+128, bn:bn+BN] = act(A @ Bt^T + bias (+ addin))
// SMEM rows: 16 data uint32 + 4 pad (stride 20) => conflict-free LDSM.
// ---------------------------------------------------------------------------
template <int BN, int WARPS_M, int WARPS_N, int K, int NTOT, bool RELU,
          bool ADDIN, bool A_HALF, bool OUT_HALF>
__device__ __forceinline__ void gemm_device(
    uint32_t* smu, int bm, int bn,
    const void* __restrict__ Av, const __half* __restrict__ Bt,
    const float* __restrict__ bias, const __half* __restrict__ addin,
    void* __restrict__ Cv, int M) {
    constexpr int BM = 128;
    constexpr int BK = 32;                 // halfs per chunk
    constexpr int ST = 20;                 // uint32 row stride
    constexpr int KT = K / BK;
    constexpr int WM = BM / WARPS_M;
    constexpr int WN = BN / WARPS_N;
    constexpr int WM16 = WM / 16;
    constexpr int WN8 = WN / 8;
    constexpr int A_ST_SZ = BM * ST;
    constexpr int B_ST_SZ = BN * ST;
    constexpr int APT_F = BM * BK / (4 * 256);
    constexpr int APT_H = BM * BK / (8 * 256);
    constexpr int BPT_H = BN * BK / (8 * 256);

    uint32_t* Asm = smu;
    uint32_t* Bsm = smu + 2 * A_ST_SZ;
    const uint32_t smaddr = (uint32_t)__cvta_generic_to_shared(smu);

    const int tid = threadIdx.x;
    const int lane = tid & 31;
    const int wid = tid >> 5;
    const int wm = wid / WARPS_N;
    const int wn = wid % WARPS_N;
    const int g = lane >> 2;
    const int t = lane & 3;
    (void)g; (void)t;

    float acc[WM16][WN8][4];
#pragma unroll
    for (int i = 0; i < WM16; ++i)
#pragma unroll
        for (int j = 0; j < WN8; ++j)
#pragma unroll
            for (int q = 0; q < 4; ++q) acc[i][j][q] = 0.f;

    float4 raf[A_HALF ? 1 : APT_F];
    uint4 rah[A_HALF ? APT_H : 1];
    uint4 rb[BPT_H];

    auto load_chunk = [&](int c) {
        const int kb = c * BK;
        if (!A_HALF) {
            const float* A = (const float*)Av;
#pragma unroll
            for (int i = 0; i < APT_F; ++i) {
                int idx = tid + i * 256;
                int r = idx >> 3, c4 = idx & 7;
                int gr = bm + r;
                raf[i] = (gr < M)
                    ? *(const float4*)(A + (size_t)gr * K + kb + c4 * 4)
                    : make_float4(0.f, 0.f, 0.f, 0.f);
            }
        } else {
            const __half* A = (const __half*)Av;
#pragma unroll
            for (int i = 0; i < APT_H; ++i) {
                int idx = tid + i * 256;
                int r = idx >> 2, c8 = idx & 3;
                int gr = bm + r;
                rah[i] = (gr < M)
                    ? *(const uint4*)(A + (size_t)gr * K + kb + c8 * 8)
                    : make_uint4(0u, 0u, 0u, 0u);
            }
        }
#pragma unroll
        for (int i = 0; i < BPT_H; ++i) {
            int idx = tid + i * 256;
            int r = idx >> 2, c8 = idx & 3;
            rb[i] = *(const uint4*)(Bt + (size_t)(bn + r) * K + kb + c8 * 8);
        }
    };

    auto sts_chunk = [&](int s) {
        uint32_t* as = Asm + s * A_ST_SZ;
        uint32_t* bs = Bsm + s * B_ST_SZ;
        if (!A_HALF) {
#pragma unroll
            for (int i = 0; i < APT_F; ++i) {
                int idx = tid + i * 256;
                int r = idx >> 3, c4 = idx & 7;
                uint2 h;
                h.x = packh2(raf[i].x, raf[i].y);
                h.y = packh2(raf[i].z, raf[i].w);
                *(uint2*)(as + r * ST + c4 * 2) = h;
            }
        } else {
#pragma unroll
            for (int i = 0; i < APT_H; ++i) {
                int idx = tid + i * 256;
                int r = idx >> 2, c8 = idx & 3;
                *(uint4*)(as + r * ST + c8 * 4) = rah[i];
            }
        }
#pragma unroll
        for (int i = 0; i < BPT_H; ++i) {
            int idx = tid + i * 256;
            int r = idx >> 2, c8 = idx & 3;
            *(uint4*)(bs + r * ST + c8 * 4) = rb[i];
        }
    };

    // ldmatrix lane-derived offsets
    const int a_lrow = lane & 15;
    const int a_lcol = (lane >> 4) << 2;
    const int b_lrow = (lane & 7) + ((lane >> 4) << 3);
    const int b_lcol = ((lane >> 3) & 1) << 2;

    auto compute = [&](int s) {
        const uint32_t a_s = smaddr + (s * A_ST_SZ) * 4;
        const uint32_t b_s = smaddr + (2 * A_ST_SZ + s * B_ST_SZ) * 4;
#pragma unroll
        for (int ks = 0; ks < 2; ++ks) {
            const int kk2 = ks * 8;
            uint32_t af[WM16][4];
#pragma unroll
            for (int mi = 0; mi < WM16; ++mi) {
                uint32_t addr = a_s +
                    (((wm * WM + mi * 16 + a_lrow) * ST) + kk2 + a_lcol) * 4;
                ldsm_x4(af[mi][0], af[mi][1], af[mi][2], af[mi][3], addr);
            }
            uint32_t bf[WN8][2];
#pragma unroll
            for (int p = 0; p < WN8 / 2; ++p) {
                uint32_t addr = b_s +
                    (((wn * WN + p * 16 + b_lrow) * ST) + kk2 + b_lcol) * 4;
                ldsm_x4(bf[2 * p][0], bf[2 * p][1],
                        bf[2 * p + 1][0], bf[2 * p + 1][1], addr);
            }
#pragma unroll
            for (int mi = 0; mi < WM16; ++mi)
#pragma unroll
                for (int ni = 0; ni < WN8; ++ni)
                    mma_f16(acc[mi][ni], af[mi], bf[ni], acc[mi][ni]);
        }
    };

    load_chunk(0);
    sts_chunk(0);
    __syncthreads();

#pragma unroll 1
    for (int c = 0; c < KT; ++c) {
        if (c + 1 < KT) load_chunk(c + 1);
        compute(c & 1);
        if (c + 1 < KT) {
            sts_chunk((c + 1) & 1);
            __syncthreads();
        }
    }

    // Epilogue
    const int g2 = lane >> 2;
    const int t2 = lane & 3;
#pragma unroll
    for (int mi = 0; mi < WM16; ++mi) {
        int row0 = bm + wm * WM + mi * 16 + g2;
#pragma unroll
        for (int ni = 0; ni < WN8; ++ni) {
            int col = bn + wn * WN + ni * 8 + 2 * t2;
            float bx = bias[col], by = bias[col + 1];
            float2 v0, v1;
            v0.x = acc[mi][ni][0] + bx; v0.y = acc[mi][ni][1] + by;
            v1.x = acc[mi][ni][2] + bx; v1.y = acc[mi][ni][3] + by;
            if (ADDIN) {
                if (row0 < M) {
                    float2 a0 = __half22float2(
                        *(const __half2*)(addin + (size_t)row0 * NTOT + col));
                    v0.x += a0.x; v0.y += a0.y;
                }
                if (row0 + 8 < M) {
                    float2 a1 = __half22float2(
                        *(const __half2*)(addin + (size_t)(row0 + 8) * NTOT + col));
                    v1.x += a1.x; v1.y += a1.y;
                }
            }
            if (RELU) {
                v0.x = fmaxf(v0.x, 0.f); v0.y = fmaxf(v0.y, 0.f);
                v1.x = fmaxf(v1.x, 0.f); v1.y = fmaxf(v1.y, 0.f);
            }
            if (OUT_HALF) {
                __half* C = (__half*)Cv;
                if (row0 < M)
                    *(__half2*)(C + (size_t)row0 * NTOT + col) =
                        __floats2half2_rn(v0.x, v0.y);
                if (row0 + 8 < M)
                    *(__half2*)(C + (size_t)(row0 + 8) * NTOT + col) =
                        __floats2half2_rn(v1.x, v1.y);
            } else {
                float* C = (float*)Cv;
                if (row0 < M)     *(float2*)(C + (size_t)row0 * NTOT + col) = v0;
                if (row0 + 8 < M) *(float2*)(C + (size_t)(row0 + 8) * NTOT + col) = v1;
            }
        }
    }
}

// ---------------------------------------------------------------------------
// Standalone GEMM kernel
// ---------------------------------------------------------------------------
template <int BN, int WARPS_M, int WARPS_N, int K, int NTOT, bool RELU,
          bool ADDIN, bool A_HALF, bool OUT_HALF>
__global__ void __launch_bounds__(256, 2)
gemm_kernel(const void* __restrict__ A, const __half* __restrict__ Bt,
            const float* __restrict__ bias, const __half* __restrict__ addin,
            void* __restrict__ C, int M) {
    extern __shared__ uint32_t smu[];
    gemm_device<BN, WARPS_M, WARPS_N, K, NTOT, RELU, ADDIN, A_HALF, OUT_HALF>(
        smu, blockIdx.x * 128, blockIdx.y * BN, A, Bt, bias, addin, C, M);
}

// ---------------------------------------------------------------------------
// het A: GEMM (x fp32 -> p1 fp16) || gather1 (x fp32 -> m0 fp16)
// ---------------------------------------------------------------------------
__global__ void __launch_bounds__(256, 2)
hetA_kernel(const float* __restrict__ x, const __half* __restrict__ Bt1s,
            const float* __restrict__ b1, __half* __restrict__ p1,
            const int* __restrict__ src0, const int* __restrict__ rp0,
            uint2* __restrict__ m0, int nGemm) {
    extern __shared__ uint32_t smu[];
    int idx = blockIdx.x;
    if (idx < nGemm) {
        int bn_i = idx & 1;            // GY = 2
        int bm_i = idx >> 1;
        gemm_device<128, 2, 4, F_IN, F_H, false, false, false, true>(
            smu, bm_i * 128, bn_i * 128, x, Bt1s, b1, nullptr, p1, N1);
    } else {
        gather_f32_to_f16<32>((idx - nGemm) * 8, (const float4*)x, src0, rp0,
                              m0, N1);
    }
}

// ---------------------------------------------------------------------------
// het D: GEMM (h1 fp16 -> out fp32) || gather2 (z2 fp16 -> m2 fp32)
// ---------------------------------------------------------------------------
__global__ void __launch_bounds__(256, 2)
hetD_kernel(const __half* __restrict__ h1, const __half* __restrict__ Bt2s,
            const float* __restrict__ b2, float* __restrict__ out,
            const __half* __restrict__ z2, const int* __restrict__ src1,
            const int* __restrict__ rp1, float4* __restrict__ m2, int nGemm) {
    extern __shared__ uint32_t smu[];
    int idx = blockIdx.x;
    if (idx < nGemm) {
        gemm_device<64, 4, 2, F_H, F_OUT, false, false, true, false>(
            smu, idx * 128, 0, h1, Bt2s, b2, nullptr, out, N2);
    } else {
        gather_f16_to_f32<16>((idx - nGemm) * 16, (const uint2*)z2, src1, rp1,
                              m2, N2);
    }
}

// ---------------------------------------------------------------------------
// out += m2
// ---------------------------------------------------------------------------
__global__ void add_kernel(const float4* __restrict__ a,
                           const float4* __restrict__ b,
                           float4* __restrict__ o, int n4) {
    int i = blockIdx.x * blockDim.x + threadIdx.x;
    if (i >= n4) return;
    float4 va = a[i], vb = b[i];
    va.x += vb.x; va.y += vb.y; va.z += vb.z; va.w += vb.w;
    o[i] = va;
}

// ---------------------------------------------------------------------------
// Launch
// ---------------------------------------------------------------------------
extern "C" void kernel_launch(void* const* d_in, const int* in_sizes, int n_in,
                              void* d_out, int out_size) {
    const float* x    = (const float*)d_in[0];
    const int*   src0 = (const int*)d_in[1];
    const int*   dst0 = (const int*)d_in[2];
    const int*   src1 = (const int*)d_in[3];
    const int*   dst1 = (const int*)d_in[4];
    const float* Ws1  = (const float*)d_in[7];
    const float* Wn1  = (const float*)d_in[8];
    const float* b1   = (const float*)d_in[9];
    const float* Ws2  = (const float*)d_in[10];
    const float* Wn2  = (const float*)d_in[11];
    const float* b2   = (const float*)d_in[12];
    float*       out  = (float*)d_out;

    __half *m0, *p1, *h1, *z2, *Bt1s, *Bt1n, *Bt2s, *Bt2n;
    float *m2, *zeros;
    int *rp0, *rp1;
    cudaGetSymbolAddress((void**)&m0,   g_m0);
    cudaGetSymbolAddress((void**)&p1,   g_p1);
    cudaGetSymbolAddress((void**)&h1,   g_h1);
    cudaGetSymbolAddress((void**)&z2,   g_z2);
    cudaGetSymbolAddress((void**)&m2,   g_m2);
    cudaGetSymbolAddress((void**)&rp0,  g_rp0);
    cudaGetSymbolAddress((void**)&rp1,  g_rp1);
    cudaGetSymbolAddress((void**)&Bt1s, g_Bt1s);
    cudaGetSymbolAddress((void**)&Bt1n, g_Bt1n);
    cudaGetSymbolAddress((void**)&Bt2s, g_Bt2s);
    cudaGetSymbolAddress((void**)&Bt2n, g_Bt2n);
    cudaGetSymbolAddress((void**)&zeros, g_zeros);

    constexpr int SMEM_128 = 2 * (128 * 20 + 128 * 20) * 4;  // 40960
    constexpr int SMEM_64  = 2 * (128 * 20 + 64 * 20) * 4;   // 30720

    // --- 1. fused prep ---
    {
        int grid = NB_RP0 + NB_RP1 + 256 + 256 + 64 + 64;
        prep_kernel<<<grid, 256>>>(dst0, dst1, Ws1, Wn1, Ws2, Wn2,
                                   rp0, rp1, Bt1s, Bt1n, Bt2s, Bt2n);
    }

    // --- 2. het A: gather1 || p1 = x @ Ws1 + b1 ---
    {
        int nGemm = ((N1 + 127) / 128) * 2;   // 1564
        int nGather = (N1 + 7) / 8;           // 12500
        hetA_kernel<<<nGemm + nGather, 256, SMEM_128>>>(
            x, Bt1s, b1, p1, src0, rp0, (uint2*)m0, nGemm);
    }

    // --- 3. B: h1 = relu(m0 @ Wn1 + p1) ---
    {
        dim3 grid((N1 + 127) / 128, F_H / 128);
        gemm_kernel<128, 2, 4, F_IN, F_H, true, true, true, true>
            <<<grid, 256, SMEM_128>>>(m0, Bt1n, zeros, p1, h1, N1);
    }

    // --- 4. C: z2 = h1 @ Wn2 (fp16 out) ---
    {
        dim3 grid((N1 + 127) / 128, 1);
        gemm_kernel<64, 4, 2, F_H, F_OUT, false, false, true, true>
            <<<grid, 256, SMEM_64>>>(h1, Bt2n, zeros, nullptr, z2, N1);
    }

    // --- 5. het D: gather2 || out = h1[:50k] @ Ws2 + b2 ---
    {
        int nGemm = (N2 + 127) / 128;         // 391
        int nGather = (N2 + 15) / 16;         // 3125
        hetD_kernel<<<nGemm + nGather, 256, SMEM_64>>>(
            h1, Bt2s, b2, out, z2, src1, rp1, (float4*)m2, nGemm);
    }

    // --- 6. out += m2 ---
    {
        int n4 = N2 * F_OUT / 4;
        add_kernel<<<(n4 + 255) / 256, 256>>>(
            (const float4*)out, (const float4*)m2, (float4*)out, n4);
    }
}

// round 8
// speedup vs baseline: 2.6441x; 1.1631x over previous
#include <cuda_runtime.h>
#include <cuda_fp16.h>
#include <cstdint>
#include <cstddef>

// ---------------------------------------------------------------------------
// Problem constants (fixed shapes)
// ---------------------------------------------------------------------------
#define N0 200000
#define N1 100000
#define N2 50000
#define E0 1600000
#define E1 800000
#define F_IN 128
#define F_H  256
#define F_OUT 64

// ---------------------------------------------------------------------------
// Scratch (device globals; no allocation allowed)
// ---------------------------------------------------------------------------
__device__ __half g_xh[(size_t)N0 * F_IN];        // x in fp16 (51.2 MB)
__device__ __half g_m0[(size_t)N1 * F_IN];        // layer-1 neighbor means (fp16)
__device__ __half g_p1[(size_t)N1 * F_H];         // x @ Ws1 + b1 (fp16)
__device__ __half g_h1[(size_t)N1 * F_H];         // hidden activations (fp16)
__device__ __half g_z2[(size_t)N1 * F_OUT];       // h1 @ Wn2 (fp16)
__device__ float  g_m2[(size_t)N2 * F_OUT];       // gathered means of z2 (fp32)
__device__ int    g_rp0[N1 + 1];                  // CSR row ptr layer 1
__device__ int    g_rp1[N2 + 1];                  // CSR row ptr layer 2
__device__ __half g_Bt1s[(size_t)F_H * F_IN];     // Ws1  [256N x 128K] K-major fp16
__device__ __half g_Bt1n[(size_t)F_H * F_IN];     // Wn1  [256N x 128K] K-major fp16
__device__ __half g_Bt2s[(size_t)F_OUT * F_H];    // Ws2  [64N x 256K]  K-major fp16
__device__ __half g_Bt2n[(size_t)F_OUT * F_H];    // Wn2  [64N x 256K]  K-major fp16
__device__ float  g_zeros[F_H];                   // stays zero

// ---------------------------------------------------------------------------
// Helpers
// ---------------------------------------------------------------------------
__device__ __forceinline__ void mma_f16(float* d, const uint32_t* a,
                                        const uint32_t* b, const float* c) {
    asm("mma.sync.aligned.m16n8k16.row.col.f32.f16.f16.f32 "
        "{%0,%1,%2,%3}, {%4,%5,%6,%7}, {%8,%9}, {%10,%11,%12,%13};"
        : "=f"(d[0]), "=f"(d[1]), "=f"(d[2]), "=f"(d[3])
        : "r"(a[0]), "r"(a[1]), "r"(a[2]), "r"(a[3]),
          "r"(b[0]), "r"(b[1]),
          "f"(c[0]), "f"(c[1]), "f"(c[2]), "f"(c[3]));
}
__device__ __forceinline__ void ldsm_x4(uint32_t& r0, uint32_t& r1,
                                        uint32_t& r2, uint32_t& r3,
                                        uint32_t saddr) {
    asm volatile("ldmatrix.sync.aligned.m8n8.x4.shared.b16 {%0,%1,%2,%3}, [%4];"
                 : "=r"(r0), "=r"(r1), "=r"(r2), "=r"(r3) : "r"(saddr));
}
__device__ __forceinline__ uint32_t packh2(float x, float y) {
    __half2 h = __floats2half2_rn(x, y);
    return *(uint32_t*)&h;
}

// ---------------------------------------------------------------------------
// Fused prep kernel: x->fp16 convert + CSR scatter (both layers) + 4 transposes
// ---------------------------------------------------------------------------
#define NB_XH  (N0 * F_IN / 8 / 256)        // 12500 (8 halfs per thread)
#define NB_RP0 ((E0 + 255) / 256)           // 6250
#define NB_RP1 ((E1 + 255) / 256)           // 3125
__global__ void __launch_bounds__(256)
prep_kernel(const float* __restrict__ x,
            const int* __restrict__ dst0, const int* __restrict__ dst1,
            const float* __restrict__ Ws1, const float* __restrict__ Wn1,
            const float* __restrict__ Ws2, const float* __restrict__ Wn2,
            __half* __restrict__ xh,
            int* __restrict__ rp0, int* __restrict__ rp1,
            __half* __restrict__ Bt1s, __half* __restrict__ Bt1n,
            __half* __restrict__ Bt2s, __half* __restrict__ Bt2n) {
    int b = blockIdx.x, tid = threadIdx.x;
    if (b < NB_XH) {
        size_t base = ((size_t)b * 256 + tid) * 8;
        float4 v0 = *(const float4*)(x + base);
        float4 v1 = *(const float4*)(x + base + 4);
        uint4 o;
        o.x = packh2(v0.x, v0.y); o.y = packh2(v0.z, v0.w);
        o.z = packh2(v1.x, v1.y); o.w = packh2(v1.z, v1.w);
        *(uint4*)(xh + base) = o;
    } else if (b < NB_XH + NB_RP0) {
        int i = (b - NB_XH) * 256 + tid;
        if (i < E0) {
            int d = dst0[i];
            int prev = (i == 0) ? -1 : dst0[i - 1];
            for (int n = prev + 1; n <= d; ++n) rp0[n] = i;
            if (i == E0 - 1)
                for (int n = d + 1; n <= N1; ++n) rp0[n] = E0;
        }
    } else if (b < NB_XH + NB_RP0 + NB_RP1) {
        int i = (b - NB_XH - NB_RP0) * 256 + tid;
        if (i < E1) {
            int d = dst1[i];
            int prev = (i == 0) ? -1 : dst1[i - 1];
            for (int n = prev + 1; n <= d; ++n) rp1[n] = i;
            if (i == E1 - 1)
                for (int n = d + 1; n <= N2; ++n) rp1[n] = E1;
        }
    } else if (b < NB_XH + NB_RP0 + NB_RP1 + 256) {
        int n = b - (NB_XH + NB_RP0 + NB_RP1);
        if (tid < F_IN) Bt1s[(size_t)n * F_IN + tid] =
            __float2half(Ws1[(size_t)tid * F_H + n]);
    } else if (b < NB_XH + NB_RP0 + NB_RP1 + 512) {
        int n = b - (NB_XH + NB_RP0 + NB_RP1 + 256);
        if (tid < F_IN) Bt1n[(size_t)n * F_IN + tid] =
            __float2half(Wn1[(size_t)tid * F_H + n]);
    } else if (b < NB_XH + NB_RP0 + NB_RP1 + 576) {
        int n = b - (NB_XH + NB_RP0 + NB_RP1 + 512);
        Bt2s[(size_t)n * F_H + tid] = __float2half(Ws2[(size_t)tid * F_OUT + n]);
    } else {
        int n = b - (NB_XH + NB_RP0 + NB_RP1 + 576);
        Bt2n[(size_t)n * F_H + tid] = __float2half(Wn2[(size_t)tid * F_OUT + n]);
    }
}

// ---------------------------------------------------------------------------
// Gather-mean bodies
// ---------------------------------------------------------------------------
// fp16 feat, uint4 lanes (8 halfs), fp32 accumulate -> fp16 out. V lanes/node.
template <int V>
__device__ __forceinline__ void gather_h2h(
    int nodeBase, const uint4* __restrict__ feat, const int* __restrict__ src,
    const int* __restrict__ rp, uint4* __restrict__ out, int nNodes) {
    int local = threadIdx.x / V;
    int lane = threadIdx.x % V;
    int gid = nodeBase + local;
    if (gid >= nNodes) return;
    int s = rp[gid], e = rp[gid + 1];
    float acc[8];
#pragma unroll
    for (int j = 0; j < 8; ++j) acc[j] = 0.f;
    int i = s;
    for (; i + 1 < e; i += 2) {
        uint4 u0 = feat[(size_t)src[i] * V + lane];
        uint4 u1 = feat[(size_t)src[i + 1] * V + lane];
        const __half2* h0 = (const __half2*)&u0;
        const __half2* h1 = (const __half2*)&u1;
#pragma unroll
        for (int j = 0; j < 4; ++j) {
            float2 f0 = __half22float2(h0[j]);
            float2 f1 = __half22float2(h1[j]);
            acc[2 * j] += f0.x + f1.x;
            acc[2 * j + 1] += f0.y + f1.y;
        }
    }
    if (i < e) {
        uint4 u = feat[(size_t)src[i] * V + lane];
        const __half2* h = (const __half2*)&u;
#pragma unroll
        for (int j = 0; j < 4; ++j) {
            float2 f = __half22float2(h[j]);
            acc[2 * j] += f.x;
            acc[2 * j + 1] += f.y;
        }
    }
    float inv = 1.f / fmaxf((float)(e - s), 1.f);
    uint4 o;
    o.x = packh2(acc[0] * inv, acc[1] * inv);
    o.y = packh2(acc[2] * inv, acc[3] * inv);
    o.z = packh2(acc[4] * inv, acc[5] * inv);
    o.w = packh2(acc[6] * inv, acc[7] * inv);
    out[(size_t)gid * V + lane] = o;
}

// fp16 feat (uint2 = 4 halfs per lane) -> fp32 float4 out. V lanes per node.
template <int V>
__device__ __forceinline__ void gather_f16_to_f32(
    int nodeBase, const uint2* __restrict__ feat, const int* __restrict__ src,
    const int* __restrict__ rp, float4* __restrict__ out, int nNodes) {
    int local = threadIdx.x / V;
    int lane = threadIdx.x % V;
    int gid = nodeBase + local;
    if (gid >= nNodes) return;
    int s = rp[gid], e = rp[gid + 1];
    float4 acc = make_float4(0.f, 0.f, 0.f, 0.f);
    for (int i = s; i < e; ++i) {
        uint2 u = feat[(size_t)src[i] * V + lane];
        float2 lo = __half22float2(*(__half2*)&u.x);
        float2 hi = __half22float2(*(__half2*)&u.y);
        acc.x += lo.x; acc.y += lo.y; acc.z += hi.x; acc.w += hi.y;
    }
    float inv = 1.f / fmaxf((float)(e - s), 1.f);
    acc.x *= inv; acc.y *= inv; acc.z *= inv; acc.w *= inv;
    out[(size_t)gid * V + lane] = acc;
}

// ---------------------------------------------------------------------------
// fp16 m16n8k16 mma.sync GEMM device body (ldmatrix fragment loads)
// SMEM rows: 16 data uint32 + 4 pad (stride 20) => conflict-free LDSM.
// ---------------------------------------------------------------------------
template <int BN, int WARPS_M, int WARPS_N, int K, int NTOT, bool RELU,
          bool ADDIN, bool OUT_HALF>
__device__ __forceinline__ void gemm_device(
    uint32_t* smu, int bm, int bn,
    const __half* __restrict__ A, const __half* __restrict__ Bt,
    const float* __restrict__ bias, const __half* __restrict__ addin,
    void* __restrict__ Cv, int M) {
    constexpr int BM = 128;
    constexpr int BK = 32;                 // halfs per chunk
    constexpr int ST = 20;                 // uint32 row stride
    constexpr int KT = K / BK;
    constexpr int WM = BM / WARPS_M;
    constexpr int WN = BN / WARPS_N;
    constexpr int WM16 = WM / 16;
    constexpr int WN8 = WN / 8;
    constexpr int A_ST_SZ = BM * ST;
    constexpr int B_ST_SZ = BN * ST;
    constexpr int APT_H = BM * BK / (8 * 256);
    constexpr int BPT_H = BN * BK / (8 * 256);

    uint32_t* Asm = smu;
    uint32_t* Bsm = smu + 2 * A_ST_SZ;
    const uint32_t smaddr = (uint32_t)__cvta_generic_to_shared(smu);

    const int tid = threadIdx.x;
    const int lane = tid & 31;
    const int wid = tid >> 5;
    const int wm = wid / WARPS_N;
    const int wn = wid % WARPS_N;

    float acc[WM16][WN8][4];
#pragma unroll
    for (int i = 0; i < WM16; ++i)
#pragma unroll
        for (int j = 0; j < WN8; ++j)
#pragma unroll
            for (int q = 0; q < 4; ++q) acc[i][j][q] = 0.f;

    uint4 rah[APT_H], rb[BPT_H];

    auto load_chunk = [&](int c) {
        const int kb = c * BK;
#pragma unroll
        for (int i = 0; i < APT_H; ++i) {
            int idx = tid + i * 256;
            int r = idx >> 2, c8 = idx & 3;
            int gr = bm + r;
            rah[i] = (gr < M)
                ? *(const uint4*)(A + (size_t)gr * K + kb + c8 * 8)
                : make_uint4(0u, 0u, 0u, 0u);
        }
#pragma unroll
        for (int i = 0; i < BPT_H; ++i) {
            int idx = tid + i * 256;
            int r = idx >> 2, c8 = idx & 3;
            rb[i] = *(const uint4*)(Bt + (size_t)(bn + r) * K + kb + c8 * 8);
        }
    };

    auto sts_chunk = [&](int s) {
        uint32_t* as = Asm + s * A_ST_SZ;
        uint32_t* bs = Bsm + s * B_ST_SZ;
#pragma unroll
        for (int i = 0; i < APT_H; ++i) {
            int idx = tid + i * 256;
            int r = idx >> 2, c8 = idx & 3;
            *(uint4*)(as + r * ST + c8 * 4) = rah[i];
        }
#pragma unroll
        for (int i = 0; i < BPT_H; ++i) {
            int idx = tid + i * 256;
            int r = idx >> 2, c8 = idx & 3;
            *(uint4*)(bs + r * ST + c8 * 4) = rb[i];
        }
    };

    const int a_lrow = lane & 15;
    const int a_lcol = (lane >> 4) << 2;
    const int b_lrow = (lane & 7) + ((lane >> 4) << 3);
    const int b_lcol = ((lane >> 3) & 1) << 2;

    auto compute = [&](int s) {
        const uint32_t a_s = smaddr + (s * A_ST_SZ) * 4;
        const uint32_t b_s = smaddr + (2 * A_ST_SZ + s * B_ST_SZ) * 4;
#pragma unroll
        for (int ks = 0; ks < 2; ++ks) {
            const int kk2 = ks * 8;
            uint32_t af[WM16][4];
#pragma unroll
            for (int mi = 0; mi < WM16; ++mi) {
                uint32_t addr = a_s +
                    (((wm * WM + mi * 16 + a_lrow) * ST) + kk2 + a_lcol) * 4;
                ldsm_x4(af[mi][0], af[mi][1], af[mi][2], af[mi][3], addr);
            }
            uint32_t bf[WN8][2];
#pragma unroll
            for (int p = 0; p < WN8 / 2; ++p) {
                uint32_t addr = b_s +
                    (((wn * WN + p * 16 + b_lrow) * ST) + kk2 + b_lcol) * 4;
                ldsm_x4(bf[2 * p][0], bf[2 * p][1],
                        bf[2 * p + 1][0], bf[2 * p + 1][1], addr);
            }
#pragma unroll
            for (int mi = 0; mi < WM16; ++mi)
#pragma unroll
                for (int ni = 0; ni < WN8; ++ni)
                    mma_f16(acc[mi][ni], af[mi], bf[ni], acc[mi][ni]);
        }
    };

    load_chunk(0);
    sts_chunk(0);
    __syncthreads();

#pragma unroll 1
    for (int c = 0; c < KT; ++c) {
        if (c + 1 < KT) load_chunk(c + 1);
        compute(c & 1);
        if (c + 1 < KT) {
            sts_chunk((c + 1) & 1);
            __syncthreads();
        }
    }

    // Epilogue
    const int g2 = lane >> 2;
    const int t2 = lane & 3;
#pragma unroll
    for (int mi = 0; mi < WM16; ++mi) {
        int row0 = bm + wm * WM + mi * 16 + g2;
#pragma unroll
        for (int ni = 0; ni < WN8; ++ni) {
            int col = bn + wn * WN + ni * 8 + 2 * t2;
            float bx = bias[col], by = bias[col + 1];
            float2 v0, v1;
            v0.x = acc[mi][ni][0] + bx; v0.y = acc[mi][ni][1] + by;
            v1.x = acc[mi][ni][2] + bx; v1.y = acc[mi][ni][3] + by;
            if (ADDIN) {
                if (row0 < M) {
                    float2 a0 = __half22float2(
                        *(const __half2*)(addin + (size_t)row0 * NTOT + col));
                    v0.x += a0.x; v0.y += a0.y;
                }
                if (row0 + 8 < M) {
                    float2 a1 = __half22float2(
                        *(const __half2*)(addin + (size_t)(row0 + 8) * NTOT + col));
                    v1.x += a1.x; v1.y += a1.y;
                }
            }
            if (RELU) {
                v0.x = fmaxf(v0.x, 0.f); v0.y = fmaxf(v0.y, 0.f);
                v1.x = fmaxf(v1.x, 0.f); v1.y = fmaxf(v1.y, 0.f);
            }
            if (OUT_HALF) {
                __half* C = (__half*)Cv;
                if (row0 < M)
                    *(__half2*)(C + (size_t)row0 * NTOT + col) =
                        __floats2half2_rn(v0.x, v0.y);
                if (row0 + 8 < M)
                    *(__half2*)(C + (size_t)(row0 + 8) * NTOT + col) =
                        __floats2half2_rn(v1.x, v1.y);
            } else {
                float* C = (float*)Cv;
                if (row0 < M)     *(float2*)(C + (size_t)row0 * NTOT + col) = v0;
                if (row0 + 8 < M) *(float2*)(C + (size_t)(row0 + 8) * NTOT + col) = v1;
            }
        }
    }
}

// ---------------------------------------------------------------------------
// Standalone GEMM kernel
// ---------------------------------------------------------------------------
template <int BN, int WARPS_M, int WARPS_N, int K, int NTOT, bool RELU,
          bool ADDIN, bool OUT_HALF>
__global__ void __launch_bounds__(256, 2)
gemm_kernel(const __half* __restrict__ A, const __half* __restrict__ Bt,
            const float* __restrict__ bias, const __half* __restrict__ addin,
            void* __restrict__ C, int M) {
    extern __shared__ uint32_t smu[];
    gemm_device<BN, WARPS_M, WARPS_N, K, NTOT, RELU, ADDIN, OUT_HALF>(
        smu, blockIdx.x * 128, blockIdx.y * BN, A, Bt, bias, addin, C, M);
}

// ---------------------------------------------------------------------------
// het A: GEMM (xh fp16 -> p1 fp16) || gather1 (xh fp16 -> m0 fp16)
// ---------------------------------------------------------------------------
__global__ void __launch_bounds__(256, 2)
hetA_kernel(const __half* __restrict__ xh, const __half* __restrict__ Bt1s,
            const float* __restrict__ b1, __half* __restrict__ p1,
            const int* __restrict__ src0, const int* __restrict__ rp0,
            uint4* __restrict__ m0, int nGemm) {
    extern __shared__ uint32_t smu[];
    int idx = blockIdx.x;
    if (idx < nGemm) {
        int bn_i = idx & 1;            // GY = 2
        int bm_i = idx >> 1;
        gemm_device<128, 2, 4, F_IN, F_H, false, false, true>(
            smu, bm_i * 128, bn_i * 128, xh, Bt1s, b1, nullptr, p1, N1);
    } else {
        gather_h2h<16>((idx - nGemm) * 16, (const uint4*)xh, src0, rp0, m0, N1);
    }
}

// ---------------------------------------------------------------------------
// het D: GEMM (h1 fp16 -> out fp32) || gather2 (z2 fp16 -> m2 fp32)
// ---------------------------------------------------------------------------
__global__ void __launch_bounds__(256, 2)
hetD_kernel(const __half* __restrict__ h1, const __half* __restrict__ Bt2s,
            const float* __restrict__ b2, float* __restrict__ out,
            const __half* __restrict__ z2, const int* __restrict__ src1,
            const int* __restrict__ rp1, float4* __restrict__ m2, int nGemm) {
    extern __shared__ uint32_t smu[];
    int idx = blockIdx.x;
    if (idx < nGemm) {
        gemm_device<64, 4, 2, F_H, F_OUT, false, false, false>(
            smu, idx * 128, 0, h1, Bt2s, b2, nullptr, out, N2);
    } else {
        gather_f16_to_f32<16>((idx - nGemm) * 16, (const uint2*)z2, src1, rp1,
                              m2, N2);
    }
}

// ---------------------------------------------------------------------------
// out += m2
// ---------------------------------------------------------------------------
__global__ void add_kernel(const float4* __restrict__ a,
                           const float4* __restrict__ b,
                           float4* __restrict__ o, int n4) {
    int i = blockIdx.x * blockDim.x + threadIdx.x;
    if (i >= n4) return;
    float4 va = a[i], vb = b[i];
    va.x += vb.x; va.y += vb.y; va.z += vb.z; va.w += vb.w;
    o[i] = va;
}

// ---------------------------------------------------------------------------
// Launch
// ---------------------------------------------------------------------------
extern "C" void kernel_launch(void* const* d_in, const int* in_sizes, int n_in,
                              void* d_out, int out_size) {
    const float* x    = (const float*)d_in[0];
    const int*   src0 = (const int*)d_in[1];
    const int*   dst0 = (const int*)d_in[2];
    const int*   src1 = (const int*)d_in[3];
    const int*   dst1 = (const int*)d_in[4];
    const float* Ws1  = (const float*)d_in[7];
    const float* Wn1  = (const float*)d_in[8];
    const float* b1   = (const float*)d_in[9];
    const float* Ws2  = (const float*)d_in[10];
    const float* Wn2  = (const float*)d_in[11];
    const float* b2   = (const float*)d_in[12];
    float*       out  = (float*)d_out;

    __half *xh, *m0, *p1, *h1, *z2, *Bt1s, *Bt1n, *Bt2s, *Bt2n;
    float *m2, *zeros;
    int *rp0, *rp1;
    cudaGetSymbolAddress((void**)&xh,   g_xh);
    cudaGetSymbolAddress((void**)&m0,   g_m0);
    cudaGetSymbolAddress((void**)&p1,   g_p1);
    cudaGetSymbolAddress((void**)&h1,   g_h1);
    cudaGetSymbolAddress((void**)&z2,   g_z2);
    cudaGetSymbolAddress((void**)&m2,   g_m2);
    cudaGetSymbolAddress((void**)&rp0,  g_rp0);
    cudaGetSymbolAddress((void**)&rp1,  g_rp1);
    cudaGetSymbolAddress((void**)&Bt1s, g_Bt1s);
    cudaGetSymbolAddress((void**)&Bt1n, g_Bt1n);
    cudaGetSymbolAddress((void**)&Bt2s, g_Bt2s);
    cudaGetSymbolAddress((void**)&Bt2n, g_Bt2n);
    cudaGetSymbolAddress((void**)&zeros, g_zeros);

    constexpr int SMEM_128 = 2 * (128 * 20 + 128 * 20) * 4;  // 40960
    constexpr int SMEM_64  = 2 * (128 * 20 + 64 * 20) * 4;   // 30720

    // --- 1. fused prep (x->fp16, CSR ptrs, weight transposes) ---
    {
        int grid = NB_XH + NB_RP0 + NB_RP1 + 256 + 256 + 64 + 64;
        prep_kernel<<<grid, 256>>>(x, dst0, dst1, Ws1, Wn1, Ws2, Wn2,
                                   xh, rp0, rp1, Bt1s, Bt1n, Bt2s, Bt2n);
    }

    // --- 2. het A: gather1 (xh) || p1 = xh @ Ws1 + b1 ---
    {
        int nGemm = ((N1 + 127) / 128) * 2;   // 1564
        int nGather = (N1 + 15) / 16;         // 6250
        hetA_kernel<<<nGemm + nGather, 256, SMEM_128>>>(
            xh, Bt1s, b1, p1, src0, rp0, (uint4*)m0, nGemm);
    }

    // --- 3. B: h1 = relu(m0 @ Wn1 + p1) ---
    {
        dim3 grid((N1 + 127) / 128, F_H / 128);
        gemm_kernel<128, 2, 4, F_IN, F_H, true, true, true>
            <<<grid, 256, SMEM_128>>>(m0, Bt1n, zeros, p1, h1, N1);
    }

    // --- 4. C: z2 = h1 @ Wn2 (fp16 out) ---
    {
        dim3 grid((N1 + 127) / 128, 1);
        gemm_kernel<64, 4, 2, F_H, F_OUT, false, false, true>
            <<<grid, 256, SMEM_64>>>(h1, Bt2n, zeros, nullptr, z2, N1);
    }

    // --- 5. het D: gather2 || out = h1[:50k] @ Ws2 + b2 ---
    {
        int nGemm = (N2 + 127) / 128;         // 391
        int nGather = (N2 + 15) / 16;         // 3125
        hetD_kernel<<<nGemm + nGather, 256, SMEM_64>>>(
            h1, Bt2s, b2, out, z2, src1, rp1, (float4*)m2, nGemm);
    }

    // --- 6. out += m2 ---
    {
        int n4 = N2 * F_OUT / 4;
        add_kernel<<<(n4 + 255) / 256, 256>>>(
            (const float4*)out, (const float4*)m2, (float4*)out, n4);
    }
}

// round 9
// speedup vs baseline: 3.3386x; 1.2627x over previous
#include <cuda_runtime.h>
#include <cuda_fp16.h>
#include <cstdint>
#include <cstddef>

// ---------------------------------------------------------------------------
// Problem constants (fixed shapes)
// ---------------------------------------------------------------------------
#define N0 200000
#define N1 100000
#define N2 50000
#define E0 1600000
#define E1 800000
#define F_IN 128
#define F_H  256
#define F_OUT 64

// ---------------------------------------------------------------------------
// Scratch (device globals; no allocation allowed)
// ---------------------------------------------------------------------------
__device__ __half g_xh[(size_t)N0 * F_IN];        // x in fp16 (51.2 MB)
__device__ __half g_m0[(size_t)N1 * F_IN];        // layer-1 neighbor means (fp16)
__device__ __half g_p1[(size_t)N1 * F_H];         // x @ Ws1 + b1 (fp16)
__device__ __half g_h1[(size_t)N1 * F_H];         // hidden activations (fp16)
__device__ __half g_z2[(size_t)N1 * F_OUT];       // h1 @ Wn2 (fp16)
__device__ float  g_m2[(size_t)N2 * F_OUT];       // gathered means of z2 (fp32)
__device__ int    g_rp0[N1 + 1];                  // CSR row ptr layer 1
__device__ int    g_rp1[N2 + 1];                  // CSR row ptr layer 2
__device__ __half g_Bt1s[(size_t)F_H * F_IN];     // Ws1  [256N x 128K] K-major fp16
__device__ __half g_Bt1n[(size_t)F_H * F_IN];     // Wn1  [256N x 128K] K-major fp16
__device__ __half g_Bt2s[(size_t)F_OUT * F_H];    // Ws2  [64N x 256K]  K-major fp16
__device__ __half g_Bt2n[(size_t)F_OUT * F_H];    // Wn2  [64N x 256K]  K-major fp16
__device__ float  g_zeros[F_H];                   // stays zero

// ---------------------------------------------------------------------------
// Helpers
// ---------------------------------------------------------------------------
__device__ __forceinline__ void mma_f16(float* d, const uint32_t* a,
                                        const uint32_t* b, const float* c) {
    asm("mma.sync.aligned.m16n8k16.row.col.f32.f16.f16.f32 "
        "{%0,%1,%2,%3}, {%4,%5,%6,%7}, {%8,%9}, {%10,%11,%12,%13};"
        : "=f"(d[0]), "=f"(d[1]), "=f"(d[2]), "=f"(d[3])
        : "r"(a[0]), "r"(a[1]), "r"(a[2]), "r"(a[3]),
          "r"(b[0]), "r"(b[1]),
          "f"(c[0]), "f"(c[1]), "f"(c[2]), "f"(c[3]));
}
__device__ __forceinline__ void ldsm_x4(uint32_t& r0, uint32_t& r1,
                                        uint32_t& r2, uint32_t& r3,
                                        uint32_t saddr) {
    asm volatile("ldmatrix.sync.aligned.m8n8.x4.shared.b16 {%0,%1,%2,%3}, [%4];"
                 : "=r"(r0), "=r"(r1), "=r"(r2), "=r"(r3) : "r"(saddr));
}
__device__ __forceinline__ uint32_t packh2(float x, float y) {
    __half2 h = __floats2half2_rn(x, y);
    return *(uint32_t*)&h;
}

// ---------------------------------------------------------------------------
// Fused prep kernel: x->fp16 convert + CSR scatter (both layers) + 4 transposes
// ---------------------------------------------------------------------------
#define NB_XH  (N0 * F_IN / 8 / 256)        // 12500
#define NB_RP0 ((E0 + 255) / 256)           // 6250
#define NB_RP1 ((E1 + 255) / 256)           // 3125
__global__ void __launch_bounds__(256)
prep_kernel(const float* __restrict__ x,
            const int* __restrict__ dst0, const int* __restrict__ dst1,
            const float* __restrict__ Ws1, const float* __restrict__ Wn1,
            const float* __restrict__ Ws2, const float* __restrict__ Wn2,
            __half* __restrict__ xh,
            int* __restrict__ rp0, int* __restrict__ rp1,
            __half* __restrict__ Bt1s, __half* __restrict__ Bt1n,
            __half* __restrict__ Bt2s, __half* __restrict__ Bt2n) {
    int b = blockIdx.x, tid = threadIdx.x;
    if (b < NB_XH) {
        size_t base = ((size_t)b * 256 + tid) * 8;
        float4 v0 = *(const float4*)(x + base);
        float4 v1 = *(const float4*)(x + base + 4);
        uint4 o;
        o.x = packh2(v0.x, v0.y); o.y = packh2(v0.z, v0.w);
        o.z = packh2(v1.x, v1.y); o.w = packh2(v1.z, v1.w);
        *(uint4*)(xh + base) = o;
    } else if (b < NB_XH + NB_RP0) {
        int i = (b - NB_XH) * 256 + tid;
        if (i < E0) {
            int d = dst0[i];
            int prev = (i == 0) ? -1 : dst0[i - 1];
            for (int n = prev + 1; n <= d; ++n) rp0[n] = i;
            if (i == E0 - 1)
                for (int n = d + 1; n <= N1; ++n) rp0[n] = E0;
        }
    } else if (b < NB_XH + NB_RP0 + NB_RP1) {
        int i = (b - NB_XH - NB_RP0) * 256 + tid;
        if (i < E1) {
            int d = dst1[i];
            int prev = (i == 0) ? -1 : dst1[i - 1];
            for (int n = prev + 1; n <= d; ++n) rp1[n] = i;
            if (i == E1 - 1)
                for (int n = d + 1; n <= N2; ++n) rp1[n] = E1;
        }
    } else if (b < NB_XH + NB_RP0 + NB_RP1 + 256) {
        int n = b - (NB_XH + NB_RP0 + NB_RP1);
        if (tid < F_IN) Bt1s[(size_t)n * F_IN + tid] =
            __float2half(Ws1[(size_t)tid * F_H + n]);
    } else if (b < NB_XH + NB_RP0 + NB_RP1 + 512) {
        int n = b - (NB_XH + NB_RP0 + NB_RP1 + 256);
        if (tid < F_IN) Bt1n[(size_t)n * F_IN + tid] =
            __float2half(Wn1[(size_t)tid * F_H + n]);
    } else if (b < NB_XH + NB_RP0 + NB_RP1 + 576) {
        int n = b - (NB_XH + NB_RP0 + NB_RP1 + 512);
        Bt2s[(size_t)n * F_H + tid] = __float2half(Ws2[(size_t)tid * F_OUT + n]);
    } else {
        int n = b - (NB_XH + NB_RP0 + NB_RP1 + 576);
        Bt2n[(size_t)n * F_H + tid] = __float2half(Wn2[(size_t)tid * F_OUT + n]);
    }
}

// ---------------------------------------------------------------------------
// Standalone gather kernels (no smem -> full occupancy; run on side stream)
// ---------------------------------------------------------------------------
// gather1: fp16 feat rows (16 uint4 lanes = 256B), 4-edge unroll, fp16 out.
__global__ void __launch_bounds__(256)
gather1_kernel(const uint4* __restrict__ feat, const int* __restrict__ src,
               const int* __restrict__ rp, uint4* __restrict__ out) {
    constexpr int V = 16;
    int t = blockIdx.x * 256 + threadIdx.x;
    int gid = t / V;
    int lane = t % V;
    if (gid >= N1) return;
    int s = rp[gid], e = rp[gid + 1];
    float acc[8];
#pragma unroll
    for (int j = 0; j < 8; ++j) acc[j] = 0.f;
    int i = s;
    for (; i + 3 < e; i += 4) {
        int s0 = src[i], s1 = src[i + 1], s2 = src[i + 2], s3 = src[i + 3];
        uint4 u0 = feat[(size_t)s0 * V + lane];
        uint4 u1 = feat[(size_t)s1 * V + lane];
        uint4 u2 = feat[(size_t)s2 * V + lane];
        uint4 u3 = feat[(size_t)s3 * V + lane];
        const __half2* h0 = (const __half2*)&u0;
        const __half2* h1 = (const __half2*)&u1;
        const __half2* h2 = (const __half2*)&u2;
        const __half2* h3 = (const __half2*)&u3;
#pragma unroll
        for (int j = 0; j < 4; ++j) {
            float2 f0 = __half22float2(h0[j]);
            float2 f1 = __half22float2(h1[j]);
            float2 f2 = __half22float2(h2[j]);
            float2 f3 = __half22float2(h3[j]);
            acc[2 * j]     += (f0.x + f1.x) + (f2.x + f3.x);
            acc[2 * j + 1] += (f0.y + f1.y) + (f2.y + f3.y);
        }
    }
    for (; i < e; ++i) {
        uint4 u = feat[(size_t)src[i] * V + lane];
        const __half2* h = (const __half2*)&u;
#pragma unroll
        for (int j = 0; j < 4; ++j) {
            float2 f = __half22float2(h[j]);
            acc[2 * j] += f.x;
            acc[2 * j + 1] += f.y;
        }
    }
    float inv = 1.f / fmaxf((float)(e - s), 1.f);
    uint4 o;
    o.x = packh2(acc[0] * inv, acc[1] * inv);
    o.y = packh2(acc[2] * inv, acc[3] * inv);
    o.z = packh2(acc[4] * inv, acc[5] * inv);
    o.w = packh2(acc[6] * inv, acc[7] * inv);
    out[(size_t)gid * V + lane] = o;
}

// gather2: fp16 feat rows (16 uint2 lanes = 128B), fp32 out, 2-edge unroll.
__global__ void __launch_bounds__(256)
gather2_kernel(const uint2* __restrict__ feat, const int* __restrict__ src,
               const int* __restrict__ rp, float4* __restrict__ out) {
    constexpr int V = 16;
    int t = blockIdx.x * 256 + threadIdx.x;
    int gid = t / V;
    int lane = t % V;
    if (gid >= N2) return;
    int s = rp[gid], e = rp[gid + 1];
    float4 acc = make_float4(0.f, 0.f, 0.f, 0.f);
    int i = s;
    for (; i + 1 < e; i += 2) {
        uint2 u0 = feat[(size_t)src[i] * V + lane];
        uint2 u1 = feat[(size_t)src[i + 1] * V + lane];
        float2 a0 = __half22float2(*(__half2*)&u0.x);
        float2 b0 = __half22float2(*(__half2*)&u0.y);
        float2 a1 = __half22float2(*(__half2*)&u1.x);
        float2 b1 = __half22float2(*(__half2*)&u1.y);
        acc.x += a0.x + a1.x; acc.y += a0.y + a1.y;
        acc.z += b0.x + b1.x; acc.w += b0.y + b1.y;
    }
    if (i < e) {
        uint2 u = feat[(size_t)src[i] * V + lane];
        float2 a = __half22float2(*(__half2*)&u.x);
        float2 b = __half22float2(*(__half2*)&u.y);
        acc.x += a.x; acc.y += a.y; acc.z += b.x; acc.w += b.y;
    }
    float inv = 1.f / fmaxf((float)(e - s), 1.f);
    acc.x *= inv; acc.y *= inv; acc.z *= inv; acc.w *= inv;
    out[(size_t)gid * V + lane] = acc;
}

// ---------------------------------------------------------------------------
// fp16 m16n8k16 mma.sync GEMM (ldmatrix fragment loads)
// ---------------------------------------------------------------------------
template <int BN, int WARPS_M, int WARPS_N, int K, int NTOT, bool RELU,
          bool ADDIN, bool OUT_HALF>
__global__ void __launch_bounds__(256, 2)
gemm_kernel(const __half* __restrict__ A, const __half* __restrict__ Bt,
            const float* __restrict__ bias, const __half* __restrict__ addin,
            void* __restrict__ Cv, int M) {
    constexpr int BM = 128;
    constexpr int BK = 32;
    constexpr int ST = 20;
    constexpr int KT = K / BK;
    constexpr int WM = BM / WARPS_M;
    constexpr int WN = BN / WARPS_N;
    constexpr int WM16 = WM / 16;
    constexpr int WN8 = WN / 8;
    constexpr int A_ST_SZ = BM * ST;
    constexpr int B_ST_SZ = BN * ST;
    constexpr int APT_H = BM * BK / (8 * 256);
    constexpr int BPT_H = BN * BK / (8 * 256);

    extern __shared__ uint32_t smu[];
    uint32_t* Asm = smu;
    uint32_t* Bsm = smu + 2 * A_ST_SZ;
    const uint32_t smaddr = (uint32_t)__cvta_generic_to_shared(smu);

    const int bm = blockIdx.x * BM;
    const int bn = blockIdx.y * BN;
    const int tid = threadIdx.x;
    const int lane = tid & 31;
    const int wid = tid >> 5;
    const int wm = wid / WARPS_N;
    const int wn = wid % WARPS_N;

    float acc[WM16][WN8][4];
#pragma unroll
    for (int i = 0; i < WM16; ++i)
#pragma unroll
        for (int j = 0; j < WN8; ++j)
#pragma unroll
            for (int q = 0; q < 4; ++q) acc[i][j][q] = 0.f;

    uint4 rah[APT_H], rb[BPT_H];

    auto load_chunk = [&](int c) {
        const int kb = c * BK;
#pragma unroll
        for (int i = 0; i < APT_H; ++i) {
            int idx = tid + i * 256;
            int r = idx >> 2, c8 = idx & 3;
            int gr = bm + r;
            rah[i] = (gr < M)
                ? *(const uint4*)(A + (size_t)gr * K + kb + c8 * 8)
                : make_uint4(0u, 0u, 0u, 0u);
        }
#pragma unroll
        for (int i = 0; i < BPT_H; ++i) {
            int idx = tid + i * 256;
            int r = idx >> 2, c8 = idx & 3;
            rb[i] = *(const uint4*)(Bt + (size_t)(bn + r) * K + kb + c8 * 8);
        }
    };

    auto sts_chunk = [&](int s) {
        uint32_t* as = Asm + s * A_ST_SZ;
        uint32_t* bs = Bsm + s * B_ST_SZ;
#pragma unroll
        for (int i = 0; i < APT_H; ++i) {
            int idx = tid + i * 256;
            int r = idx >> 2, c8 = idx & 3;
            *(uint4*)(as + r * ST + c8 * 4) = rah[i];
        }
#pragma unroll
        for (int i = 0; i < BPT_H; ++i) {
            int idx = tid + i * 256;
            int r = idx >> 2, c8 = idx & 3;
            *(uint4*)(bs + r * ST + c8 * 4) = rb[i];
        }
    };

    const int a_lrow = lane & 15;
    const int a_lcol = (lane >> 4) << 2;
    const int b_lrow = (lane & 7) + ((lane >> 4) << 3);
    const int b_lcol = ((lane >> 3) & 1) << 2;

    auto compute = [&](int s) {
        const uint32_t a_s = smaddr + (s * A_ST_SZ) * 4;
        const uint32_t b_s = smaddr + (2 * A_ST_SZ + s * B_ST_SZ) * 4;
#pragma unroll
        for (int ks = 0; ks < 2; ++ks) {
            const int kk2 = ks * 8;
            uint32_t af[WM16][4];
#pragma unroll
            for (int mi = 0; mi < WM16; ++mi) {
                uint32_t addr = a_s +
                    (((wm * WM + mi * 16 + a_lrow) * ST) + kk2 + a_lcol) * 4;
                ldsm_x4(af[mi][0], af[mi][1], af[mi][2], af[mi][3], addr);
            }
            uint32_t bf[WN8][2];
#pragma unroll
            for (int p = 0; p < WN8 / 2; ++p) {
                uint32_t addr = b_s +
                    (((wn * WN + p * 16 + b_lrow) * ST) + kk2 + b_lcol) * 4;
                ldsm_x4(bf[2 * p][0], bf[2 * p][1],
                        bf[2 * p + 1][0], bf[2 * p + 1][1], addr);
            }
#pragma unroll
            for (int mi = 0; mi < WM16; ++mi)
#pragma unroll
                for (int ni = 0; ni < WN8; ++ni)
                    mma_f16(acc[mi][ni], af[mi], bf[ni], acc[mi][ni]);
        }
    };

    load_chunk(0);
    sts_chunk(0);
    __syncthreads();

#pragma unroll 1
    for (int c = 0; c < KT; ++c) {
        if (c + 1 < KT) load_chunk(c + 1);
        compute(c & 1);
        if (c + 1 < KT) {
            sts_chunk((c + 1) & 1);
            __syncthreads();
        }
    }

    const int g2 = lane >> 2;
    const int t2 = lane & 3;
#pragma unroll
    for (int mi = 0; mi < WM16; ++mi) {
        int row0 = bm + wm * WM + mi * 16 + g2;
#pragma unroll
        for (int ni = 0; ni < WN8; ++ni) {
            int col = bn + wn * WN + ni * 8 + 2 * t2;
            float bx = bias[col], by = bias[col + 1];
            float2 v0, v1;
            v0.x = acc[mi][ni][0] + bx; v0.y = acc[mi][ni][1] + by;
            v1.x = acc[mi][ni][2] + bx; v1.y = acc[mi][ni][3] + by;
            if (ADDIN) {
                if (row0 < M) {
                    float2 a0 = __half22float2(
                        *(const __half2*)(addin + (size_t)row0 * NTOT + col));
                    v0.x += a0.x; v0.y += a0.y;
                }
                if (row0 + 8 < M) {
                    float2 a1 = __half22float2(
                        *(const __half2*)(addin + (size_t)(row0 + 8) * NTOT + col));
                    v1.x += a1.x; v1.y += a1.y;
                }
            }
            if (RELU) {
                v0.x = fmaxf(v0.x, 0.f); v0.y = fmaxf(v0.y, 0.f);
                v1.x = fmaxf(v1.x, 0.f); v1.y = fmaxf(v1.y, 0.f);
            }
            if (OUT_HALF) {
                __half* C = (__half*)Cv;
                if (row0 < M)
                    *(__half2*)(C + (size_t)row0 * NTOT + col) =
                        __floats2half2_rn(v0.x, v0.y);
                if (row0 + 8 < M)
                    *(__half2*)(C + (size_t)(row0 + 8) * NTOT + col) =
                        __floats2half2_rn(v1.x, v1.y);
            } else {
                float* C = (float*)Cv;
                if (row0 < M)     *(float2*)(C + (size_t)row0 * NTOT + col) = v0;
                if (row0 + 8 < M) *(float2*)(C + (size_t)(row0 + 8) * NTOT + col) = v1;
            }
        }
    }
}

// ---------------------------------------------------------------------------
// out += m2
// ---------------------------------------------------------------------------
__global__ void add_kernel(const float4* __restrict__ a,
                           const float4* __restrict__ b,
                           float4* __restrict__ o, int n4) {
    int i = blockIdx.x * blockDim.x + threadIdx.x;
    if (i >= n4) return;
    float4 va = a[i], vb = b[i];
    va.x += vb.x; va.y += vb.y; va.z += vb.z; va.w += vb.w;
    o[i] = va;
}

// ---------------------------------------------------------------------------
// Launch: two-stream fork-join (capture-safe event pattern)
// ---------------------------------------------------------------------------
extern "C" void kernel_launch(void* const* d_in, const int* in_sizes, int n_in,
                              void* d_out, int out_size) {
    const float* x    = (const float*)d_in[0];
    const int*   src0 = (const int*)d_in[1];
    const int*   dst0 = (const int*)d_in[2];
    const int*   src1 = (const int*)d_in[3];
    const int*   dst1 = (const int*)d_in[4];
    const float* Ws1  = (const float*)d_in[7];
    const float* Wn1  = (const float*)d_in[8];
    const float* b1   = (const float*)d_in[9];
    const float* Ws2  = (const float*)d_in[10];
    const float* Wn2  = (const float*)d_in[11];
    const float* b2   = (const float*)d_in[12];
    float*       out  = (float*)d_out;

    __half *xh, *m0, *p1, *h1, *z2, *Bt1s, *Bt1n, *Bt2s, *Bt2n;
    float *m2, *zeros;
    int *rp0, *rp1;
    cudaGetSymbolAddress((void**)&xh,   g_xh);
    cudaGetSymbolAddress((void**)&m0,   g_m0);
    cudaGetSymbolAddress((void**)&p1,   g_p1);
    cudaGetSymbolAddress((void**)&h1,   g_h1);
    cudaGetSymbolAddress((void**)&z2,   g_z2);
    cudaGetSymbolAddress((void**)&m2,   g_m2);
    cudaGetSymbolAddress((void**)&rp0,  g_rp0);
    cudaGetSymbolAddress((void**)&rp1,  g_rp1);
    cudaGetSymbolAddress((void**)&Bt1s, g_Bt1s);
    cudaGetSymbolAddress((void**)&Bt1n, g_Bt1n);
    cudaGetSymbolAddress((void**)&Bt2s, g_Bt2s);
    cudaGetSymbolAddress((void**)&Bt2n, g_Bt2n);
    cudaGetSymbolAddress((void**)&zeros, g_zeros);

    static cudaStream_t s1 = nullptr;
    static cudaEvent_t evF1 = nullptr, evJ1 = nullptr, evF2 = nullptr,
                       evJ2 = nullptr;
    if (s1 == nullptr) {
        cudaStreamCreateWithFlags(&s1, cudaStreamNonBlocking);
        cudaEventCreateWithFlags(&evF1, cudaEventDisableTiming);
        cudaEventCreateWithFlags(&evJ1, cudaEventDisableTiming);
        cudaEventCreateWithFlags(&evF2, cudaEventDisableTiming);
        cudaEventCreateWithFlags(&evJ2, cudaEventDisableTiming);
    }

    constexpr int SMEM_128 = 2 * (128 * 20 + 128 * 20) * 4;  // 40960
    constexpr int SMEM_64  = 2 * (128 * 20 + 64 * 20) * 4;   // 30720

    // --- 1. fused prep ---
    {
        int grid = NB_XH + NB_RP0 + NB_RP1 + 256 + 256 + 64 + 64;
        prep_kernel<<<grid, 256>>>(x, dst0, dst1, Ws1, Wn1, Ws2, Wn2,
                                   xh, rp0, rp1, Bt1s, Bt1n, Bt2s, Bt2n);
    }

    // --- 2. fork: gather1 on s1  ||  gemmA on main stream ---
    cudaEventRecord(evF1, 0);
    cudaStreamWaitEvent(s1, evF1, 0);
    gather1_kernel<<<(N1 * 16 + 255) / 256, 256, 0, s1>>>(
        (const uint4*)xh, src0, rp0, (uint4*)m0);
    cudaEventRecord(evJ1, s1);

    {
        dim3 grid((N1 + 127) / 128, F_H / 128);
        gemm_kernel<128, 2, 4, F_IN, F_H, false, false, true>
            <<<grid, 256, SMEM_128>>>(xh, Bt1s, b1, nullptr, p1, N1);
    }
    cudaStreamWaitEvent(0, evJ1, 0);

    // --- 3. B: h1 = relu(m0 @ Wn1 + p1) ---
    {
        dim3 grid((N1 + 127) / 128, F_H / 128);
        gemm_kernel<128, 2, 4, F_IN, F_H, true, true, true>
            <<<grid, 256, SMEM_128>>>(m0, Bt1n, zeros, p1, h1, N1);
    }

    // --- 4. C: z2 = h1 @ Wn2 (fp16 out) ---
    {
        dim3 grid((N1 + 127) / 128, 1);
        gemm_kernel<64, 4, 2, F_H, F_OUT, false, false, true>
            <<<grid, 256, SMEM_64>>>(h1, Bt2n, zeros, nullptr, z2, N1);
    }

    // --- 5. fork: gather2 on s1  ||  gemmD on main stream ---
    cudaEventRecord(evF2, 0);
    cudaStreamWaitEvent(s1, evF2, 0);
    gather2_kernel<<<(N2 * 16 + 255) / 256, 256, 0, s1>>>(
        (const uint2*)z2, src1, rp1, (float4*)m2);
    cudaEventRecord(evJ2, s1);

    {
        dim3 grid((N2 + 127) / 128, 1);
        gemm_kernel<64, 4, 2, F_H, F_OUT, false, false, false>
            <<<grid, 256, SMEM_64>>>(h1, Bt2s, b2, nullptr, out, N2);
    }
    cudaStreamWaitEvent(0, evJ2, 0);

    // --- 6. out += m2 ---
    {
        int n4 = N2 * F_OUT / 4;
        add_kernel<<<(n4 + 255) / 256, 256>>>(
            (const float4*)out, (const float4*)m2, (float4*)out, n4);
    }
}

// round 10
// speedup vs baseline: 3.4003x; 1.0185x over previous
#include <cuda_runtime.h>
#include <cuda_fp16.h>
#include <cstdint>
#include <cstddef>

// ---------------------------------------------------------------------------
// Problem constants (fixed shapes)
// ---------------------------------------------------------------------------
#define N0 200000
#define N1 100000
#define N2 50000
#define E0 1600000
#define E1 800000
#define F_IN 128
#define F_H  256
#define F_OUT 64

// ---------------------------------------------------------------------------
// Scratch (device globals; no allocation allowed)
// ---------------------------------------------------------------------------
__device__ __half g_xh[(size_t)N0 * F_IN];        // x in fp16 (51.2 MB)
__device__ __half g_m0[(size_t)N1 * F_IN];        // layer-1 neighbor means (fp16)
__device__ __half g_p1[(size_t)N1 * F_H];         // x @ Ws1 + b1 (fp16)
__device__ __half g_h1[(size_t)N1 * F_H];         // hidden activations (fp16)
__device__ __half g_z2[(size_t)N1 * F_OUT];       // h1 @ Wn2 (fp16)
__device__ int    g_rp0[N1 + 1];                  // CSR row ptr layer 1
__device__ int    g_rp1[N2 + 1];                  // CSR row ptr layer 2
__device__ __half g_Bt1s[(size_t)F_H * F_IN];     // Ws1  [256N x 128K] K-major fp16
__device__ __half g_Bt1n[(size_t)F_H * F_IN];     // Wn1  [256N x 128K] K-major fp16
__device__ __half g_Bt2s[(size_t)F_OUT * F_H];    // Ws2  [64N x 256K]  K-major fp16
__device__ __half g_Bt2n[(size_t)F_OUT * F_H];    // Wn2  [64N x 256K]  K-major fp16
__device__ float  g_zeros[F_H];                   // stays zero

// ---------------------------------------------------------------------------
// Helpers
// ---------------------------------------------------------------------------
__device__ __forceinline__ void mma_f16(float* d, const uint32_t* a,
                                        const uint32_t* b, const float* c) {
    asm("mma.sync.aligned.m16n8k16.row.col.f32.f16.f16.f32 "
        "{%0,%1,%2,%3}, {%4,%5,%6,%7}, {%8,%9}, {%10,%11,%12,%13};"
        : "=f"(d[0]), "=f"(d[1]), "=f"(d[2]), "=f"(d[3])
        : "r"(a[0]), "r"(a[1]), "r"(a[2]), "r"(a[3]),
          "r"(b[0]), "r"(b[1]),
          "f"(c[0]), "f"(c[1]), "f"(c[2]), "f"(c[3]));
}
__device__ __forceinline__ void ldsm_x4(uint32_t& r0, uint32_t& r1,
                                        uint32_t& r2, uint32_t& r3,
                                        uint32_t saddr) {
    asm volatile("ldmatrix.sync.aligned.m8n8.x4.shared.b16 {%0,%1,%2,%3}, [%4];"
                 : "=r"(r0), "=r"(r1), "=r"(r2), "=r"(r3) : "r"(saddr));
}
__device__ __forceinline__ uint32_t packh2(float x, float y) {
    __half2 h = __floats2half2_rn(x, y);
    return *(uint32_t*)&h;
}

// ---------------------------------------------------------------------------
// prepA: rp0 scatter + Bt1s/Bt1n transposes (everything gemmA/gather1/B need
// except xh). prepB: rp1 scatter + Bt2s/Bt2n transposes.
// ---------------------------------------------------------------------------
#define NB_RP0 ((E0 + 255) / 256)           // 6250
#define NB_RP1 ((E1 + 255) / 256)           // 3125
__global__ void __launch_bounds__(256)
prepA_kernel(const int* __restrict__ dst0,
             const float* __restrict__ Ws1, const float* __restrict__ Wn1,
             int* __restrict__ rp0,
             __half* __restrict__ Bt1s, __half* __restrict__ Bt1n) {
    int b = blockIdx.x, tid = threadIdx.x;
    if (b < NB_RP0) {
        int i = b * 256 + tid;
        if (i < E0) {
            int d = dst0[i];
            int prev = (i == 0) ? -1 : dst0[i - 1];
            for (int n = prev + 1; n <= d; ++n) rp0[n] = i;
            if (i == E0 - 1)
                for (int n = d + 1; n <= N1; ++n) rp0[n] = E0;
        }
    } else if (b < NB_RP0 + 256) {
        int n = b - NB_RP0;
        if (tid < F_IN) Bt1s[(size_t)n * F_IN + tid] =
            __float2half(Ws1[(size_t)tid * F_H + n]);
    } else {
        int n = b - (NB_RP0 + 256);
        if (tid < F_IN) Bt1n[(size_t)n * F_IN + tid] =
            __float2half(Wn1[(size_t)tid * F_H + n]);
    }
}

__global__ void __launch_bounds__(256)
prepB_kernel(const int* __restrict__ dst1,
             const float* __restrict__ Ws2, const float* __restrict__ Wn2,
             int* __restrict__ rp1,
             __half* __restrict__ Bt2s, __half* __restrict__ Bt2n) {
    int b = blockIdx.x, tid = threadIdx.x;
    if (b < NB_RP1) {
        int i = b * 256 + tid;
        if (i < E1) {
            int d = dst1[i];
            int prev = (i == 0) ? -1 : dst1[i - 1];
            for (int n = prev + 1; n <= d; ++n) rp1[n] = i;
            if (i == E1 - 1)
                for (int n = d + 1; n <= N2; ++n) rp1[n] = E1;
        }
    } else if (b < NB_RP1 + 64) {
        int n = b - NB_RP1;
        Bt2s[(size_t)n * F_H + tid] = __float2half(Ws2[(size_t)tid * F_OUT + n]);
    } else {
        int n = b - (NB_RP1 + 64);
        Bt2n[(size_t)n * F_H + tid] = __float2half(Wn2[(size_t)tid * F_OUT + n]);
    }
}

// xh = fp16(x), 8 halfs per thread
__global__ void __launch_bounds__(256)
xh_convert_kernel(const float* __restrict__ x, __half* __restrict__ xh) {
    size_t base = ((size_t)blockIdx.x * 256 + threadIdx.x) * 8;
    float4 v0 = *(const float4*)(x + base);
    float4 v1 = *(const float4*)(x + base + 4);
    uint4 o;
    o.x = packh2(v0.x, v0.y); o.y = packh2(v0.z, v0.w);
    o.z = packh2(v1.x, v1.y); o.w = packh2(v1.z, v1.w);
    *(uint4*)(xh + base) = o;
}

// ---------------------------------------------------------------------------
// gather1: fp16 feat rows (16 uint4 lanes = 256B), 4-edge unroll, fp16 out.
// ---------------------------------------------------------------------------
__global__ void __launch_bounds__(256)
gather1_kernel(const uint4* __restrict__ feat, const int* __restrict__ src,
               const int* __restrict__ rp, uint4* __restrict__ out) {
    constexpr int V = 16;
    int t = blockIdx.x * 256 + threadIdx.x;
    int gid = t / V;
    int lane = t % V;
    if (gid >= N1) return;
    int s = rp[gid], e = rp[gid + 1];
    float acc[8];
#pragma unroll
    for (int j = 0; j < 8; ++j) acc[j] = 0.f;
    int i = s;
    for (; i + 3 < e; i += 4) {
        int s0 = src[i], s1 = src[i + 1], s2 = src[i + 2], s3 = src[i + 3];
        uint4 u0 = feat[(size_t)s0 * V + lane];
        uint4 u1 = feat[(size_t)s1 * V + lane];
        uint4 u2 = feat[(size_t)s2 * V + lane];
        uint4 u3 = feat[(size_t)s3 * V + lane];
        const __half2* h0 = (const __half2*)&u0;
        const __half2* h1 = (const __half2*)&u1;
        const __half2* h2 = (const __half2*)&u2;
        const __half2* h3 = (const __half2*)&u3;
#pragma unroll
        for (int j = 0; j < 4; ++j) {
            float2 f0 = __half22float2(h0[j]);
            float2 f1 = __half22float2(h1[j]);
            float2 f2 = __half22float2(h2[j]);
            float2 f3 = __half22float2(h3[j]);
            acc[2 * j]     += (f0.x + f1.x) + (f2.x + f3.x);
            acc[2 * j + 1] += (f0.y + f1.y) + (f2.y + f3.y);
        }
    }
    for (; i < e; ++i) {
        uint4 u = feat[(size_t)src[i] * V + lane];
        const __half2* h = (const __half2*)&u;
#pragma unroll
        for (int j = 0; j < 4; ++j) {
            float2 f = __half22float2(h[j]);
            acc[2 * j] += f.x;
            acc[2 * j + 1] += f.y;
        }
    }
    float inv = 1.f / fmaxf((float)(e - s), 1.f);
    uint4 o;
    o.x = packh2(acc[0] * inv, acc[1] * inv);
    o.y = packh2(acc[2] * inv, acc[3] * inv);
    o.z = packh2(acc[4] * inv, acc[5] * inv);
    o.w = packh2(acc[6] * inv, acc[7] * inv);
    out[(size_t)gid * V + lane] = o;
}

// ---------------------------------------------------------------------------
// gather2 fused: mean of z2 rows accumulated INTO out (out += mean)
// ---------------------------------------------------------------------------
__global__ void __launch_bounds__(256)
gather2_fused_kernel(const uint2* __restrict__ feat, const int* __restrict__ src,
                     const int* __restrict__ rp, float4* __restrict__ out) {
    constexpr int V = 16;
    int t = blockIdx.x * 256 + threadIdx.x;
    int gid = t / V;
    int lane = t % V;
    if (gid >= N2) return;
    int s = rp[gid], e = rp[gid + 1];
    float4 acc = make_float4(0.f, 0.f, 0.f, 0.f);
    int i = s;
    for (; i + 1 < e; i += 2) {
        uint2 u0 = feat[(size_t)src[i] * V + lane];
        uint2 u1 = feat[(size_t)src[i + 1] * V + lane];
        float2 a0 = __half22float2(*(__half2*)&u0.x);
        float2 b0 = __half22float2(*(__half2*)&u0.y);
        float2 a1 = __half22float2(*(__half2*)&u1.x);
        float2 b1 = __half22float2(*(__half2*)&u1.y);
        acc.x += a0.x + a1.x; acc.y += a0.y + a1.y;
        acc.z += b0.x + b1.x; acc.w += b0.y + b1.y;
    }
    if (i < e) {
        uint2 u = feat[(size_t)src[i] * V + lane];
        float2 a = __half22float2(*(__half2*)&u.x);
        float2 b = __half22float2(*(__half2*)&u.y);
        acc.x += a.x; acc.y += a.y; acc.z += b.x; acc.w += b.y;
    }
    float inv = 1.f / fmaxf((float)(e - s), 1.f);
    float4 cur = out[(size_t)gid * V + lane];
    cur.x += acc.x * inv; cur.y += acc.y * inv;
    cur.z += acc.z * inv; cur.w += acc.w * inv;
    out[(size_t)gid * V + lane] = cur;
}

// ---------------------------------------------------------------------------
// fp16 m16n8k16 mma.sync GEMM (ldmatrix fragment loads)
// A fp32 (A_HALF=0, converted at staging) or fp16 (A_HALF=1).
// ---------------------------------------------------------------------------
template <int BN, int WARPS_M, int WARPS_N, int K, int NTOT, bool RELU,
          bool ADDIN, bool A_HALF, bool OUT_HALF>
__global__ void __launch_bounds__(256, 2)
gemm_kernel(const void* __restrict__ Av, const __half* __restrict__ Bt,
            const float* __restrict__ bias, const __half* __restrict__ addin,
            void* __restrict__ Cv, int M) {
    constexpr int BM = 128;
    constexpr int BK = 32;
    constexpr int ST = 20;
    constexpr int KT = K / BK;
    constexpr int WM = BM / WARPS_M;
    constexpr int WN = BN / WARPS_N;
    constexpr int WM16 = WM / 16;
    constexpr int WN8 = WN / 8;
    constexpr int A_ST_SZ = BM * ST;
    constexpr int B_ST_SZ = BN * ST;
    constexpr int APT_F = BM * BK / (4 * 256);
    constexpr int APT_H = BM * BK / (8 * 256);
    constexpr int BPT_H = BN * BK / (8 * 256);

    extern __shared__ uint32_t smu[];
    uint32_t* Asm = smu;
    uint32_t* Bsm = smu + 2 * A_ST_SZ;
    const uint32_t smaddr = (uint32_t)__cvta_generic_to_shared(smu);

    const int bm = blockIdx.x * BM;
    const int bn = blockIdx.y * BN;
    const int tid = threadIdx.x;
    const int lane = tid & 31;
    const int wid = tid >> 5;
    const int wm = wid / WARPS_N;
    const int wn = wid % WARPS_N;

    float acc[WM16][WN8][4];
#pragma unroll
    for (int i = 0; i < WM16; ++i)
#pragma unroll
        for (int j = 0; j < WN8; ++j)
#pragma unroll
            for (int q = 0; q < 4; ++q) acc[i][j][q] = 0.f;

    float4 raf[A_HALF ? 1 : APT_F];
    uint4 rah[A_HALF ? APT_H : 1];
    uint4 rb[BPT_H];

    auto load_chunk = [&](int c) {
        const int kb = c * BK;
        if (!A_HALF) {
            const float* A = (const float*)Av;
#pragma unroll
            for (int i = 0; i < APT_F; ++i) {
                int idx = tid + i * 256;
                int r = idx >> 3, c4 = idx & 7;
                int gr = bm + r;
                raf[i] = (gr < M)
                    ? *(const float4*)(A + (size_t)gr * K + kb + c4 * 4)
                    : make_float4(0.f, 0.f, 0.f, 0.f);
            }
        } else {
            const __half* A = (const __half*)Av;
#pragma unroll
            for (int i = 0; i < APT_H; ++i) {
                int idx = tid + i * 256;
                int r = idx >> 2, c8 = idx & 3;
                int gr = bm + r;
                rah[i] = (gr < M)
                    ? *(const uint4*)(A + (size_t)gr * K + kb + c8 * 8)
                    : make_uint4(0u, 0u, 0u, 0u);
            }
        }
#pragma unroll
        for (int i = 0; i < BPT_H; ++i) {
            int idx = tid + i * 256;
            int r = idx >> 2, c8 = idx & 3;
            rb[i] = *(const uint4*)(Bt + (size_t)(bn + r) * K + kb + c8 * 8);
        }
    };

    auto sts_chunk = [&](int s) {
        uint32_t* as = Asm + s * A_ST_SZ;
        uint32_t* bs = Bsm + s * B_ST_SZ;
        if (!A_HALF) {
#pragma unroll
            for (int i = 0; i < APT_F; ++i) {
                int idx = tid + i * 256;
                int r = idx >> 3, c4 = idx & 7;
                uint2 h;
                h.x = packh2(raf[i].x, raf[i].y);
                h.y = packh2(raf[i].z, raf[i].w);
                *(uint2*)(as + r * ST + c4 * 2) = h;
            }
        } else {
#pragma unroll
            for (int i = 0; i < APT_H; ++i) {
                int idx = tid + i * 256;
                int r = idx >> 2, c8 = idx & 3;
                *(uint4*)(as + r * ST + c8 * 4) = rah[i];
            }
        }
#pragma unroll
        for (int i = 0; i < BPT_H; ++i) {
            int idx = tid + i * 256;
            int r = idx >> 2, c8 = idx & 3;
            *(uint4*)(bs + r * ST + c8 * 4) = rb[i];
        }
    };

    const int a_lrow = lane & 15;
    const int a_lcol = (lane >> 4) << 2;
    const int b_lrow = (lane & 7) + ((lane >> 4) << 3);
    const int b_lcol = ((lane >> 3) & 1) << 2;

    auto compute = [&](int s) {
        const uint32_t a_s = smaddr + (s * A_ST_SZ) * 4;
        const uint32_t b_s = smaddr + (2 * A_ST_SZ + s * B_ST_SZ) * 4;
#pragma unroll
        for (int ks = 0; ks < 2; ++ks) {
            const int kk2 = ks * 8;
            uint32_t af[WM16][4];
#pragma unroll
            for (int mi = 0; mi < WM16; ++mi) {
                uint32_t addr = a_s +
                    (((wm * WM + mi * 16 + a_lrow) * ST) + kk2 + a_lcol) * 4;
                ldsm_x4(af[mi][0], af[mi][1], af[mi][2], af[mi][3], addr);
            }
            uint32_t bf[WN8][2];
#pragma unroll
            for (int p = 0; p < WN8 / 2; ++p) {
                uint32_t addr = b_s +
                    (((wn * WN + p * 16 + b_lrow) * ST) + kk2 + b_lcol) * 4;
                ldsm_x4(bf[2 * p][0], bf[2 * p][1],
                        bf[2 * p + 1][0], bf[2 * p + 1][1], addr);
            }
#pragma unroll
            for (int mi = 0; mi < WM16; ++mi)
#pragma unroll
                for (int ni = 0; ni < WN8; ++ni)
                    mma_f16(acc[mi][ni], af[mi], bf[ni], acc[mi][ni]);
        }
    };

    load_chunk(0);
    sts_chunk(0);
    __syncthreads();

#pragma unroll 1
    for (int c = 0; c < KT; ++c) {
        if (c + 1 < KT) load_chunk(c + 1);
        compute(c & 1);
        if (c + 1 < KT) {
            sts_chunk((c + 1) & 1);
            __syncthreads();
        }
    }

    const int g2 = lane >> 2;
    const int t2 = lane & 3;
#pragma unroll
    for (int mi = 0; mi < WM16; ++mi) {
        int row0 = bm + wm * WM + mi * 16 + g2;
#pragma unroll
        for (int ni = 0; ni < WN8; ++ni) {
            int col = bn + wn * WN + ni * 8 + 2 * t2;
            float bx = bias[col], by = bias[col + 1];
            float2 v0, v1;
            v0.x = acc[mi][ni][0] + bx; v0.y = acc[mi][ni][1] + by;
            v1.x = acc[mi][ni][2] + bx; v1.y = acc[mi][ni][3] + by;
            if (ADDIN) {
                if (row0 < M) {
                    float2 a0 = __half22float2(
                        *(const __half2*)(addin + (size_t)row0 * NTOT + col));
                    v0.x += a0.x; v0.y += a0.y;
                }
                if (row0 + 8 < M) {
                    float2 a1 = __half22float2(
                        *(const __half2*)(addin + (size_t)(row0 + 8) * NTOT + col));
                    v1.x += a1.x; v1.y += a1.y;
                }
            }
            if (RELU) {
                v0.x = fmaxf(v0.x, 0.f); v0.y = fmaxf(v0.y, 0.f);
                v1.x = fmaxf(v1.x, 0.f); v1.y = fmaxf(v1.y, 0.f);
            }
            if (OUT_HALF) {
                __half* C = (__half*)Cv;
                if (row0 < M)
                    *(__half2*)(C + (size_t)row0 * NTOT + col) =
                        __floats2half2_rn(v0.x, v0.y);
                if (row0 + 8 < M)
                    *(__half2*)(C + (size_t)(row0 + 8) * NTOT + col) =
                        __floats2half2_rn(v1.x, v1.y);
            } else {
                float* C = (float*)Cv;
                if (row0 < M)     *(float2*)(C + (size_t)row0 * NTOT + col) = v0;
                if (row0 + 8 < M) *(float2*)(C + (size_t)(row0 + 8) * NTOT + col) = v1;
            }
        }
    }
}

// ---------------------------------------------------------------------------
// Launch: two-stream fork-join DAG
//   prepA -> { (xh-cvt -> gather1) || (gemmA -> prepB) } -> B
//         -> { C || gemmD } -> gather2+=
// ---------------------------------------------------------------------------
extern "C" void kernel_launch(void* const* d_in, const int* in_sizes, int n_in,
                              void* d_out, int out_size) {
    const float* x    = (const float*)d_in[0];
    const int*   src0 = (const int*)d_in[1];
    const int*   dst0 = (const int*)d_in[2];
    const int*   src1 = (const int*)d_in[3];
    const int*   dst1 = (const int*)d_in[4];
    const float* Ws1  = (const float*)d_in[7];
    const float* Wn1  = (const float*)d_in[8];
    const float* b1   = (const float*)d_in[9];
    const float* Ws2  = (const float*)d_in[10];
    const float* Wn2  = (const float*)d_in[11];
    const float* b2   = (const float*)d_in[12];
    float*       out  = (float*)d_out;

    __half *xh, *m0, *p1, *h1, *z2, *Bt1s, *Bt1n, *Bt2s, *Bt2n;
    float *zeros;
    int *rp0, *rp1;
    cudaGetSymbolAddress((void**)&xh,   g_xh);
    cudaGetSymbolAddress((void**)&m0,   g_m0);
    cudaGetSymbolAddress((void**)&p1,   g_p1);
    cudaGetSymbolAddress((void**)&h1,   g_h1);
    cudaGetSymbolAddress((void**)&z2,   g_z2);
    cudaGetSymbolAddress((void**)&rp0,  g_rp0);
    cudaGetSymbolAddress((void**)&rp1,  g_rp1);
    cudaGetSymbolAddress((void**)&Bt1s, g_Bt1s);
    cudaGetSymbolAddress((void**)&Bt1n, g_Bt1n);
    cudaGetSymbolAddress((void**)&Bt2s, g_Bt2s);
    cudaGetSymbolAddress((void**)&Bt2n, g_Bt2n);
    cudaGetSymbolAddress((void**)&zeros, g_zeros);

    static cudaStream_t s1 = nullptr;
    static cudaEvent_t evF1 = nullptr, evJ1 = nullptr, evF2 = nullptr,
                       evJ2 = nullptr;
    if (s1 == nullptr) {
        cudaStreamCreateWithFlags(&s1, cudaStreamNonBlocking);
        cudaEventCreateWithFlags(&evF1, cudaEventDisableTiming);
        cudaEventCreateWithFlags(&evJ1, cudaEventDisableTiming);
        cudaEventCreateWithFlags(&evF2, cudaEventDisableTiming);
        cudaEventCreateWithFlags(&evJ2, cudaEventDisableTiming);
    }

    constexpr int SMEM_128 = 2 * (128 * 20 + 128 * 20) * 4;  // 40960
    constexpr int SMEM_64  = 2 * (128 * 20 + 64 * 20) * 4;   // 30720

    // --- 1. prepA: rp0 + Bt1s + Bt1n ---
    prepA_kernel<<<NB_RP0 + 512, 256>>>(dst0, Ws1, Wn1, rp0, Bt1s, Bt1n);

    // --- 2. fork ---
    cudaEventRecord(evF1, 0);
    cudaStreamWaitEvent(s1, evF1, 0);

    // s1: xh convert -> gather1 -> join event
    xh_convert_kernel<<<N0 * F_IN / 8 / 256, 256, 0, s1>>>(x, xh);
    gather1_kernel<<<(N1 * 16 + 255) / 256, 256, 0, s1>>>(
        (const uint4*)xh, src0, rp0, (uint4*)m0);
    cudaEventRecord(evJ1, s1);

    // main: gemmA (x fp32 -> p1 fp16), then prepB (hidden under gather1)
    {
        dim3 grid((N1 + 127) / 128, F_H / 128);
        gemm_kernel<128, 2, 4, F_IN, F_H, false, false, false, true>
            <<<grid, 256, SMEM_128>>>(x, Bt1s, b1, nullptr, p1, N1);
    }
    prepB_kernel<<<NB_RP1 + 128, 256>>>(dst1, Ws2, Wn2, rp1, Bt2s, Bt2n);
    cudaStreamWaitEvent(0, evJ1, 0);

    // --- 3. B: h1 = relu(m0 @ Wn1 + p1) ---
    {
        dim3 grid((N1 + 127) / 128, F_H / 128);
        gemm_kernel<128, 2, 4, F_IN, F_H, true, true, true, true>
            <<<grid, 256, SMEM_128>>>(m0, Bt1n, zeros, p1, h1, N1);
    }

    // --- 4. fork: gemmD on s1 || C on main ---
    cudaEventRecord(evF2, 0);
    cudaStreamWaitEvent(s1, evF2, 0);
    {
        dim3 grid((N2 + 127) / 128, 1);
        gemm_kernel<64, 4, 2, F_H, F_OUT, false, false, true, false>
            <<<grid, 256, SMEM_64, s1>>>(h1, Bt2s, b2, nullptr, out, N2);
    }
    cudaEventRecord(evJ2, s1);

    {
        dim3 grid((N1 + 127) / 128, 1);
        gemm_kernel<64, 4, 2, F_H, F_OUT, false, false, true, true>
            <<<grid, 256, SMEM_64>>>(h1, Bt2n, zeros, nullptr, z2, N1);
    }
    cudaStreamWaitEvent(0, evJ2, 0);

    // --- 5. gather2 fused: out += mean(z2 over edges) ---
    gather2_fused_kernel<<<(N2 * 16 + 255) / 256, 256>>>(
        (const uint2*)z2, src1, rp1, (float4*)out);
}